// round 9
// baseline (speedup 1.0000x reference)
#include <cuda_runtime.h>
#include <cuda_bf16.h>
#include <math.h>
#include <stdint.h>

#define S_LEN 2048
#define HID   4096
#define NH    32
#define NKV   8
#define HDIM  128
#define WINDOW 1024
#define KDIM  4096
#define NKVD  (NKV * HDIM)      // 1024

// ---------------- scratch (__device__ globals; no allocation) ----------------
__device__ __align__(256) __nv_bfloat16 g_hs_hi[S_LEN * HID];
__device__ __align__(256) __nv_bfloat16 g_hs_lo[S_LEN * HID];
__device__ __align__(256) __nv_bfloat16 g_att_hi[S_LEN * HID];
__device__ __align__(256) __nv_bfloat16 g_att_lo[S_LEN * HID];
__device__ __align__(256) __nv_bfloat16 g_Qh[S_LEN * HID];
__device__ __align__(256) __nv_bfloat16 g_Ql[S_LEN * HID];
__device__ __align__(256) __nv_bfloat16 g_Kh[S_LEN * NKVD];
__device__ __align__(256) __nv_bfloat16 g_Kl[S_LEN * NKVD];
__device__ __align__(256) __nv_bfloat16 g_Vh[S_LEN * NKVD];
__device__ __align__(256) __nv_bfloat16 g_Vl[S_LEN * NKVD];
__device__ __align__(256) __nv_bfloat16 g_Wq_hi[HID * HID];
__device__ __align__(256) __nv_bfloat16 g_Wq_lo[HID * HID];
__device__ __align__(256) __nv_bfloat16 g_Wk_hi[NKVD * HID];
__device__ __align__(256) __nv_bfloat16 g_Wk_lo[NKVD * HID];
__device__ __align__(256) __nv_bfloat16 g_Wv_hi[NKVD * HID];
__device__ __align__(256) __nv_bfloat16 g_Wv_lo[NKVD * HID];
__device__ __align__(256) __nv_bfloat16 g_Wo_hi[HID * HID];
__device__ __align__(256) __nv_bfloat16 g_Wo_lo[HID * HID];

// ---------------- helpers (baseline PTX only: sm_80-class features) ----------
__device__ __forceinline__ uint32_t smem_u32(const void* p) {
    uint32_t a;
    asm("{ .reg .u64 t; cvta.to.shared.u64 t, %1; cvt.u32.u64 %0, t; }" : "=r"(a) : "l"(p));
    return a;
}
__device__ __forceinline__ void cp16(uint32_t dst, const void* src) {
    asm volatile("cp.async.cg.shared.global [%0], [%1], 16;" :: "r"(dst), "l"(src));
}
__device__ __forceinline__ void cp_commit() {
    asm volatile("cp.async.commit_group;" ::: "memory");
}
template <int N>
__device__ __forceinline__ void cp_wait() {
    asm volatile("cp.async.wait_group %0;" :: "n"(N) : "memory");
}
__device__ __forceinline__ void ldsm_x4(uint32_t* r, uint32_t addr) {
    asm volatile("ldmatrix.sync.aligned.m8n8.x4.shared.b16 {%0,%1,%2,%3}, [%4];"
                 : "=r"(r[0]), "=r"(r[1]), "=r"(r[2]), "=r"(r[3]) : "r"(addr));
}
__device__ __forceinline__ void ldsm_x4_t(uint32_t* r, uint32_t addr) {
    asm volatile("ldmatrix.sync.aligned.m8n8.x4.trans.shared.b16 {%0,%1,%2,%3}, [%4];"
                 : "=r"(r[0]), "=r"(r[1]), "=r"(r[2]), "=r"(r[3]) : "r"(addr));
}
__device__ __forceinline__ void mma16816(float* c, const uint32_t* a,
                                         uint32_t b0, uint32_t b1) {
    asm volatile(
        "mma.sync.aligned.m16n8k16.row.col.f32.bf16.bf16.f32 "
        "{%0,%1,%2,%3}, {%4,%5,%6,%7}, {%8,%9}, {%0,%1,%2,%3};"
        : "+f"(c[0]), "+f"(c[1]), "+f"(c[2]), "+f"(c[3])
        : "r"(a[0]), "r"(a[1]), "r"(a[2]), "r"(a[3]), "r"(b0), "r"(b1));
}
__device__ __forceinline__ void packsplit(float x, float y, uint32_t& hi, uint32_t& lo) {
    __nv_bfloat16 hx = __float2bfloat16(x), hy = __float2bfloat16(y);
    __nv_bfloat16 lx = __float2bfloat16(x - __bfloat162float(hx));
    __nv_bfloat16 ly = __float2bfloat16(y - __bfloat162float(hy));
    hi = (uint32_t)__bfloat16_as_ushort(hx) | ((uint32_t)__bfloat16_as_ushort(hy) << 16);
    lo = (uint32_t)__bfloat16_as_ushort(lx) | ((uint32_t)__bfloat16_as_ushort(ly) << 16);
}

#define SWZ(off) ((off) ^ (((off) >> 3) & 0x70))

// ---------------------------------------------------------------------------
// fused split of all fp32 inputs -> bf16 hi + lo (single launch)
// ---------------------------------------------------------------------------
#define HS4 (S_LEN * HID / 4)
#define WQ4 (HID * HID / 4)
#define WK4 (NKVD * HID / 4)
#define WV4 (NKVD * HID / 4)
#define WO4 (HID * HID / 4)
#define TOT4 (HS4 + WQ4 + WK4 + WV4 + WO4)

__global__ void split_all(const float* __restrict__ hs, const float* __restrict__ Wq,
                          const float* __restrict__ Wk, const float* __restrict__ Wv,
                          const float* __restrict__ Wo)
{
    int i = blockIdx.x * blockDim.x + threadIdx.x;
    if (i >= TOT4) return;
    const float* in;
    __nv_bfloat16 *ho, *lo;
    int off;
    if (i < HS4)                         { in = hs; ho = g_hs_hi; lo = g_hs_lo; off = i; }
    else if (i < HS4 + WQ4)              { in = Wq; ho = g_Wq_hi; lo = g_Wq_lo; off = i - HS4; }
    else if (i < HS4 + WQ4 + WK4)        { in = Wk; ho = g_Wk_hi; lo = g_Wk_lo; off = i - HS4 - WQ4; }
    else if (i < HS4 + WQ4 + WK4 + WV4)  { in = Wv; ho = g_Wv_hi; lo = g_Wv_lo; off = i - HS4 - WQ4 - WK4; }
    else                                 { in = Wo; ho = g_Wo_hi; lo = g_Wo_lo; off = i - HS4 - WQ4 - WK4 - WV4; }

    float4 v = ((const float4*)in)[off];
    float x[4] = {v.x, v.y, v.z, v.w};
    unsigned short h[4], l[4];
    #pragma unroll
    for (int j = 0; j < 4; ++j) {
        __nv_bfloat16 hb = __float2bfloat16(x[j]);
        __nv_bfloat16 lb = __float2bfloat16(x[j] - __bfloat162float(hb));
        h[j] = __bfloat16_as_ushort(hb);
        l[j] = __bfloat16_as_ushort(lb);
    }
    ((ushort4*)ho)[off] = make_ushort4(h[0], h[1], h[2], h[3]);
    ((ushort4*)lo)[off] = make_ushort4(l[0], l[1], l[2], l[3]);
}

// ---------------------------------------------------------------------------
// Shared GEMM mainloop constants
// ---------------------------------------------------------------------------
#define GK 64
#define TILEB 16384
#define BUFB (4 * TILEB)

// ---------------------------------------------------------------------------
// Fused QKV projection + RoPE + hi/lo split. Logical N = 6144, grid (48, 16).
// Single-barrier-per-chunk cp.async pipeline.
// ---------------------------------------------------------------------------
__global__ void __launch_bounds__(256, 1)
gemm_qkv(const __nv_bfloat16* __restrict__ Ahi, const __nv_bfloat16* __restrict__ Alo,
         const int* __restrict__ pos,
         __nv_bfloat16* __restrict__ Qh, __nv_bfloat16* __restrict__ Ql,
         __nv_bfloat16* __restrict__ Kh, __nv_bfloat16* __restrict__ Kl,
         __nv_bfloat16* __restrict__ Vh, __nv_bfloat16* __restrict__ Vl)
{
    extern __shared__ char smraw[];
    char* smc = (char*)(((uintptr_t)smraw + 1023) & ~(uintptr_t)1023);
    const uint32_t sbase = smem_u32(smc);

    const int tid = threadIdx.x;
    const int lane = tid & 31;
    const int wid = tid >> 5;
    const int wr = wid >> 2;
    const int wc = wid & 3;
    const int bx = blockIdx.x;
    const int m0 = blockIdx.y * 128;

    const __nv_bfloat16 *Bhi, *Blo;
    int bn0;
    if (bx < 32)      { Bhi = g_Wq_hi; Blo = g_Wq_lo; bn0 = bx * 128; }
    else if (bx < 40) { Bhi = g_Wk_hi; Blo = g_Wk_lo; bn0 = (bx - 32) * 128; }
    else              { Bhi = g_Wv_hi; Blo = g_Wv_lo; bn0 = (bx - 40) * 128; }

    float acc[4][4][4];
    #pragma unroll
    for (int a = 0; a < 4; ++a)
        #pragma unroll
        for (int b = 0; b < 4; ++b)
            #pragma unroll
            for (int c = 0; c < 4; ++c) acc[a][b][c] = 0.f;

    const int NCHUNK = KDIM / GK;

    auto load_chunk = [&](int it) {
        const uint32_t bufb = sbase + (it & 1) * BUFB;
        const int k0 = it * GK;
        #pragma unroll
        for (int p = 0; p < 4; ++p) {
            int linear = tid + p * 256;
            int r = linear >> 3;
            int cb = (linear & 7) * 16;
            uint32_t sw = SWZ((uint32_t)(r * 128 + cb));
            size_t ga = (size_t)(m0 + r) * KDIM + k0 + (cb >> 1);
            size_t gb = (size_t)(bn0 + r) * KDIM + k0 + (cb >> 1);
            cp16(bufb + sw,              &Ahi[ga]);
            cp16(bufb + TILEB + sw,      &Alo[ga]);
            cp16(bufb + 2 * TILEB + sw,  &Bhi[gb]);
            cp16(bufb + 3 * TILEB + sw,  &Blo[gb]);
        }
    };

    load_chunk(0);
    cp_commit();

    const int lrow = lane & 15;
    const int lkb  = (lane >> 4) * 16;

    for (int it = 0; it < NCHUNK; ++it) {
        cp_wait<0>();          // chunk `it` landed
        __syncthreads();       // everyone sees it; everyone done reading prev buffer
        if (it + 1 < NCHUNK) { // prefetch into the buffer just freed
            load_chunk(it + 1);
            cp_commit();
        }

        const uint32_t bufb = sbase + (it & 1) * BUFB;

        #pragma unroll
        for (int ks = 0; ks < 4; ++ks) {
            uint32_t ah[4][4], al[4][4], bh[2][4], bl[2][4];
            #pragma unroll
            for (int mi = 0; mi < 4; ++mi) {
                uint32_t off = (uint32_t)((wr * 64 + mi * 16 + lrow) * 128 + ks * 32 + lkb);
                uint32_t sw = SWZ(off);
                ldsm_x4(ah[mi], bufb + sw);
                ldsm_x4(al[mi], bufb + TILEB + sw);
            }
            #pragma unroll
            for (int np = 0; np < 2; ++np) {
                uint32_t off = (uint32_t)((wc * 32 + np * 16 + lrow) * 128 + ks * 32 + lkb);
                uint32_t sw = SWZ(off);
                ldsm_x4(bh[np], bufb + 2 * TILEB + sw);
                ldsm_x4(bl[np], bufb + 3 * TILEB + sw);
            }
            #pragma unroll
            for (int mi = 0; mi < 4; ++mi)
                #pragma unroll
                for (int ni = 0; ni < 4; ++ni) {
                    uint32_t b0h = bh[ni >> 1][ni & 1], b1h = bh[ni >> 1][2 + (ni & 1)];
                    uint32_t b0l = bl[ni >> 1][ni & 1], b1l = bl[ni >> 1][2 + (ni & 1)];
                    mma16816(acc[mi][ni], ah[mi], b0h, b1h);
                    mma16816(acc[mi][ni], ah[mi], b0l, b1l);
                    mma16816(acc[mi][ni], al[mi], b0h, b1h);
                }
        }
    }

    __syncthreads();   // all MMA smem reads done before Cs overwrites tile buffers

    // ---- epilogue: stage acc in smem, RoPE (Q/K) + split, store bf16 hi/lo ----
    float* Cs = (float*)smc;                       // 128 x 132 floats (67.6 KB)
    {
        const int rb = wr * 64 + (lane >> 2);
        const int cb2 = wc * 32 + (lane & 3) * 2;
        #pragma unroll
        for (int mi = 0; mi < 4; ++mi)
            #pragma unroll
            for (int ni = 0; ni < 4; ++ni) {
                int r = rb + mi * 16, cc = cb2 + ni * 8;
                Cs[r * 132 + cc]           = acc[mi][ni][0];
                Cs[r * 132 + cc + 1]       = acc[mi][ni][1];
                Cs[(r + 8) * 132 + cc]     = acc[mi][ni][2];
                Cs[(r + 8) * 132 + cc + 1] = acc[mi][ni][3];
            }
    }
    __syncthreads();

    __nv_bfloat16 *Hout, *Lout;
    int stride, off;
    bool dorope;
    if (bx < 32)      { Hout = Qh; Lout = Ql; stride = HID;  off = bx * 128;        dorope = true; }
    else if (bx < 40) { Hout = Kh; Lout = Kl; stride = NKVD; off = (bx - 32) * 128; dorope = true; }
    else              { Hout = Vh; Lout = Vl; stride = NKVD; off = (bx - 40) * 128; dorope = false; }

    const int d0 = tid & 63;
    const int rg = tid >> 6;
    const float invf = dorope ? expf(-(float)d0 * 0.14391156831212787f) : 0.f;

    #pragma unroll 4
    for (int rr = 0; rr < 32; ++rr) {
        const int r = rg * 32 + rr;
        const int t = m0 + r;
        float x0 = Cs[r * 132 + d0];
        float x1 = Cs[r * 132 + d0 + 64];
        float y0, y1;
        if (dorope) {
            float s, c;
            sincosf((float)pos[t] * invf, &s, &c);
            y0 = x0 * c - x1 * s;
            y1 = x1 * c + x0 * s;
        } else {
            y0 = x0; y1 = x1;
        }
        __nv_bfloat16 h0 = __float2bfloat16(y0);
        __nv_bfloat16 l0 = __float2bfloat16(y0 - __bfloat162float(h0));
        __nv_bfloat16 h1 = __float2bfloat16(y1);
        __nv_bfloat16 l1 = __float2bfloat16(y1 - __bfloat162float(h1));
        size_t o = (size_t)t * stride + off + d0;
        Hout[o]      = h0;
        Lout[o]      = l0;
        Hout[o + 64] = h1;
        Lout[o + 64] = l1;
    }
}

// ---------------------------------------------------------------------------
// Generic GEMM (Wo projection): C = (Ahi+Alo)*(Bhi+Blo)^T, fp32 out.
// Single-barrier-per-chunk pipeline.
// ---------------------------------------------------------------------------
__global__ void __launch_bounds__(256, 1)
gemm_bf16x3(const __nv_bfloat16* __restrict__ Ahi, const __nv_bfloat16* __restrict__ Alo,
            const __nv_bfloat16* __restrict__ Bhi, const __nv_bfloat16* __restrict__ Blo,
            float* __restrict__ C, int M, int N, int K)
{
    extern __shared__ char smraw[];
    char* smc = (char*)(((uintptr_t)smraw + 1023) & ~(uintptr_t)1023);
    const uint32_t sbase = smem_u32(smc);

    const int tid = threadIdx.x;
    const int lane = tid & 31;
    const int wid = tid >> 5;
    const int wr = wid >> 2;
    const int wc = wid & 3;
    const int m0 = blockIdx.y * 128;
    const int n0 = blockIdx.x * 128;

    float acc[4][4][4];
    #pragma unroll
    for (int a = 0; a < 4; ++a)
        #pragma unroll
        for (int b = 0; b < 4; ++b)
            #pragma unroll
            for (int c = 0; c < 4; ++c) acc[a][b][c] = 0.f;

    const int NCHUNK = K / GK;

    auto load_chunk = [&](int it) {
        const uint32_t bufb = sbase + (it & 1) * BUFB;
        const int k0 = it * GK;
        #pragma unroll
        for (int p = 0; p < 4; ++p) {
            int linear = tid + p * 256;
            int r = linear >> 3;
            int cb = (linear & 7) * 16;
            uint32_t sw = SWZ((uint32_t)(r * 128 + cb));
            size_t ga = (size_t)(m0 + r) * K + k0 + (cb >> 1);
            size_t gb = (size_t)(n0 + r) * K + k0 + (cb >> 1);
            cp16(bufb + sw,              &Ahi[ga]);
            cp16(bufb + TILEB + sw,      &Alo[ga]);
            cp16(bufb + 2 * TILEB + sw,  &Bhi[gb]);
            cp16(bufb + 3 * TILEB + sw,  &Blo[gb]);
        }
    };

    load_chunk(0);
    cp_commit();

    const int lrow = lane & 15;
    const int lkb  = (lane >> 4) * 16;

    for (int it = 0; it < NCHUNK; ++it) {
        cp_wait<0>();
        __syncthreads();
        if (it + 1 < NCHUNK) {
            load_chunk(it + 1);
            cp_commit();
        }

        const uint32_t bufb = sbase + (it & 1) * BUFB;

        #pragma unroll
        for (int ks = 0; ks < 4; ++ks) {
            uint32_t ah[4][4], al[4][4], bh[2][4], bl[2][4];
            #pragma unroll
            for (int mi = 0; mi < 4; ++mi) {
                uint32_t off = (uint32_t)((wr * 64 + mi * 16 + lrow) * 128 + ks * 32 + lkb);
                uint32_t sw = SWZ(off);
                ldsm_x4(ah[mi], bufb + sw);
                ldsm_x4(al[mi], bufb + TILEB + sw);
            }
            #pragma unroll
            for (int np = 0; np < 2; ++np) {
                uint32_t off = (uint32_t)((wc * 32 + np * 16 + lrow) * 128 + ks * 32 + lkb);
                uint32_t sw = SWZ(off);
                ldsm_x4(bh[np], bufb + 2 * TILEB + sw);
                ldsm_x4(bl[np], bufb + 3 * TILEB + sw);
            }
            #pragma unroll
            for (int mi = 0; mi < 4; ++mi)
                #pragma unroll
                for (int ni = 0; ni < 4; ++ni) {
                    uint32_t b0h = bh[ni >> 1][ni & 1], b1h = bh[ni >> 1][2 + (ni & 1)];
                    uint32_t b0l = bl[ni >> 1][ni & 1], b1l = bl[ni >> 1][2 + (ni & 1)];
                    mma16816(acc[mi][ni], ah[mi], b0h, b1h);
                    mma16816(acc[mi][ni], ah[mi], b0l, b1l);
                    mma16816(acc[mi][ni], al[mi], b0h, b1h);
                }
        }
    }

    const int row_base = m0 + wr * 64 + (lane >> 2);
    const int col_base = n0 + wc * 32 + (lane & 3) * 2;
    #pragma unroll
    for (int mi = 0; mi < 4; ++mi)
        #pragma unroll
        for (int ni = 0; ni < 4; ++ni) {
            int r = row_base + mi * 16;
            int cc = col_base + ni * 8;
            *(float2*)&C[(size_t)r * N + cc]       = make_float2(acc[mi][ni][0], acc[mi][ni][1]);
            *(float2*)&C[(size_t)(r + 8) * N + cc] = make_float2(acc[mi][ni][2], acc[mi][ni][3]);
        }
}

// ---------------------------------------------------------------------------
// Flash attention on tensor cores (bf16x3, online softmax in registers).
// Single-barrier-per-tile KV pipeline.
// ---------------------------------------------------------------------------
#define ATT_SMEM (1024 + 3 * 65536)

__global__ void __launch_bounds__(256)
attn_mma(const __nv_bfloat16* __restrict__ Qh_g, const __nv_bfloat16* __restrict__ Ql_g,
         const __nv_bfloat16* __restrict__ Kh_g, const __nv_bfloat16* __restrict__ Kl_g,
         const __nv_bfloat16* __restrict__ Vh_g, const __nv_bfloat16* __restrict__ Vl_g,
         __nv_bfloat16* __restrict__ Oh_g, __nv_bfloat16* __restrict__ Ol_g)
{
    extern __shared__ char smraw[];
    char* smc = (char*)(((uintptr_t)smraw + 1023) & ~(uintptr_t)1023);
    const uint32_t qbase = smem_u32(smc);
    const uint32_t kvbase = qbase + 65536;

    const int tid = threadIdx.x;
    const int lane = tid & 31;
    const int w = tid >> 5;
    const int wm = w * 16;
    const int m0 = blockIdx.x * 128;
    const int h = blockIdx.y;
    const int kvh = h >> 2;
    const int lrow = lane & 15;
    const int lhi = (lane >> 4) * 16;

    auto load_q = [&]() {
        #pragma unroll
        for (int p = 0; p < 16; ++p) {
            int lin = tid + p * 256;
            int t2 = lin >> 11;
            int rem = lin & 2047;
            int row = rem >> 4;
            int c = rem & 15;
            int half = c >> 3;
            int cb = (c & 7) * 16;
            uint32_t dst = qbase + t2 * 32768 + half * 16384
                         + SWZ((uint32_t)(row * 128 + cb));
            size_t elem = (size_t)(m0 + row) * HID + h * HDIM + half * 64 + (c & 7) * 8;
            cp16(dst, (t2 ? Ql_g : Qh_g) + elem);
        }
    };
    auto load_kv = [&](int j, int b) {
        const uint32_t base = kvbase + b * 65536;
        #pragma unroll
        for (int p = 0; p < 16; ++p) {
            int lin = tid + p * 256;
            int t4 = lin >> 10;
            int rem = lin & 1023;
            int row = rem >> 4;
            int c = rem & 15;
            int half = c >> 3;
            int cb = (c & 7) * 16;
            uint32_t dst = base + t4 * 16384 + half * 8192
                         + SWZ((uint32_t)(row * 128 + cb));
            size_t elem = (size_t)(j * 64 + row) * NKVD + kvh * HDIM
                        + half * 64 + (c & 7) * 8;
            const __nv_bfloat16* src =
                (t4 < 2) ? ((t4 & 1) ? Kl_g : Kh_g) : ((t4 & 1) ? Vl_g : Vh_g);
            cp16(dst, src + elem);
        }
    };

    const int j0 = (m0 >= 1024) ? (m0 - 1023) / 64 : 0;
    const int jend = m0 / 64 + 1;

    load_q();
    load_kv(j0, 0);
    cp_commit();

    float o[16][4];
    #pragma unroll
    for (int i = 0; i < 16; ++i)
        #pragma unroll
        for (int c = 0; c < 4; ++c) o[i][c] = 0.f;
    float mst0 = -INFINITY, mst1 = -INFINITY, lst0 = 0.f, lst1 = 0.f;

    const int row0 = m0 + wm + (lane >> 2);
    const int row1 = row0 + 8;
    const float scale = 0.08838834764831845f;

    for (int j = j0; j <= jend; ++j) {
        const int b = (j - j0) & 1;
        cp_wait<0>();
        __syncthreads();
        if (j + 1 <= jend) {
            load_kv(j + 1, b ^ 1);
            cp_commit();
        }

        const uint32_t kvb = kvbase + b * 65536;

        float sf[8][4];
        #pragma unroll
        for (int i = 0; i < 8; ++i)
            #pragma unroll
            for (int c = 0; c < 4; ++c) sf[i][c] = 0.f;

        #pragma unroll
        for (int kd = 0; kd < 8; ++kd) {
            const int half = kd >> 2;
            const uint32_t koff = (uint32_t)((kd & 3) * 32 + lhi);
            uint32_t ah[4], al[4], bh[4][4], bl[4][4];
            {
                uint32_t sw = SWZ((uint32_t)((wm + lrow) * 128) + koff);
                ldsm_x4(ah, qbase + half * 16384 + sw);
                ldsm_x4(al, qbase + 32768 + half * 16384 + sw);
            }
            #pragma unroll
            for (int nb = 0; nb < 4; ++nb) {
                uint32_t sw = SWZ((uint32_t)((nb * 16 + lrow) * 128) + koff);
                ldsm_x4(bh[nb], kvb + half * 8192 + sw);
                ldsm_x4(bl[nb], kvb + 16384 + half * 8192 + sw);
            }
            #pragma unroll
            for (int ni = 0; ni < 8; ++ni) {
                const int nb = ni >> 1, s = ni & 1;
                mma16816(sf[ni], ah, bh[nb][s], bh[nb][s + 2]);
                mma16816(sf[ni], ah, bl[nb][s], bl[nb][s + 2]);
                mma16816(sf[ni], al, bh[nb][s], bh[nb][s + 2]);
            }
        }

        const int colb = j * 64 + (lane & 3) * 2;
        float rmax0 = -INFINITY, rmax1 = -INFINITY;
        #pragma unroll
        for (int ni = 0; ni < 8; ++ni) {
            int c0 = colb + ni * 8, c1 = c0 + 1;
            sf[ni][0] = (c0 <= row0 && row0 - c0 < WINDOW) ? sf[ni][0] * scale : -INFINITY;
            sf[ni][1] = (c1 <= row0 && row0 - c1 < WINDOW) ? sf[ni][1] * scale : -INFINITY;
            sf[ni][2] = (c0 <= row1 && row1 - c0 < WINDOW) ? sf[ni][2] * scale : -INFINITY;
            sf[ni][3] = (c1 <= row1 && row1 - c1 < WINDOW) ? sf[ni][3] * scale : -INFINITY;
            rmax0 = fmaxf(rmax0, fmaxf(sf[ni][0], sf[ni][1]));
            rmax1 = fmaxf(rmax1, fmaxf(sf[ni][2], sf[ni][3]));
        }
        rmax0 = fmaxf(rmax0, __shfl_xor_sync(0xffffffffu, rmax0, 1));
        rmax0 = fmaxf(rmax0, __shfl_xor_sync(0xffffffffu, rmax0, 2));
        rmax1 = fmaxf(rmax1, __shfl_xor_sync(0xffffffffu, rmax1, 1));
        rmax1 = fmaxf(rmax1, __shfl_xor_sync(0xffffffffu, rmax1, 2));

        float mn0 = fmaxf(mst0, rmax0), mn1 = fmaxf(mst1, rmax1);
        float mc0 = fmaxf(mn0, -1e30f), mc1 = fmaxf(mn1, -1e30f);
        float a0 = __expf(fmaxf(mst0, -1e30f) - mc0);
        float a1 = __expf(fmaxf(mst1, -1e30f) - mc1);
        float sum0 = 0.f, sum1 = 0.f;
        #pragma unroll
        for (int ni = 0; ni < 8; ++ni) {
            sf[ni][0] = __expf(sf[ni][0] - mc0);
            sf[ni][1] = __expf(sf[ni][1] - mc0);
            sf[ni][2] = __expf(sf[ni][2] - mc1);
            sf[ni][3] = __expf(sf[ni][3] - mc1);
            sum0 += sf[ni][0] + sf[ni][1];
            sum1 += sf[ni][2] + sf[ni][3];
        }
        sum0 += __shfl_xor_sync(0xffffffffu, sum0, 1);
        sum0 += __shfl_xor_sync(0xffffffffu, sum0, 2);
        sum1 += __shfl_xor_sync(0xffffffffu, sum1, 1);
        sum1 += __shfl_xor_sync(0xffffffffu, sum1, 2);
        mst0 = mn0; mst1 = mn1;
        lst0 = lst0 * a0 + sum0;
        lst1 = lst1 * a1 + sum1;
        #pragma unroll
        for (int nf = 0; nf < 16; ++nf) {
            o[nf][0] *= a0; o[nf][1] *= a0;
            o[nf][2] *= a1; o[nf][3] *= a1;
        }

        #pragma unroll
        for (int ks = 0; ks < 4; ++ks) {
            uint32_t ah[4], al[4];
            packsplit(sf[2 * ks][0],     sf[2 * ks][1],     ah[0], al[0]);
            packsplit(sf[2 * ks][2],     sf[2 * ks][3],     ah[1], al[1]);
            packsplit(sf[2 * ks + 1][0], sf[2 * ks + 1][1], ah[2], al[2]);
            packsplit(sf[2 * ks + 1][2], sf[2 * ks + 1][3], ah[3], al[3]);
            #pragma unroll
            for (int g = 0; g < 8; ++g) {
                const int half = g >> 2;
                uint32_t off = SWZ((uint32_t)((ks * 16 + lrow) * 128 + (g & 3) * 32) + lhi);
                uint32_t vh[4], vl[4];
                ldsm_x4_t(vh, kvb + 32768 + half * 8192 + off);
                ldsm_x4_t(vl, kvb + 49152 + half * 8192 + off);
                mma16816(o[2 * g],     ah, vh[0], vh[1]);
                mma16816(o[2 * g],     ah, vl[0], vl[1]);
                mma16816(o[2 * g],     al, vh[0], vh[1]);
                mma16816(o[2 * g + 1], ah, vh[2], vh[3]);
                mma16816(o[2 * g + 1], ah, vl[2], vl[3]);
                mma16816(o[2 * g + 1], al, vh[2], vh[3]);
            }
        }
    }

    const float inv0 = 1.f / lst0;
    const float inv1 = 1.f / lst1;
    #pragma unroll
    for (int nf = 0; nf < 16; ++nf) {
        int d = h * HDIM + nf * 8 + (lane & 3) * 2;
        size_t off0 = (size_t)row0 * HID + d;
        size_t off1 = (size_t)row1 * HID + d;
        uint32_t hi, lo;
        packsplit(o[nf][0] * inv0, o[nf][1] * inv0, hi, lo);
        *(uint32_t*)(Oh_g + off0) = hi;
        *(uint32_t*)(Ol_g + off0) = lo;
        packsplit(o[nf][2] * inv1, o[nf][3] * inv1, hi, lo);
        *(uint32_t*)(Oh_g + off1) = hi;
        *(uint32_t*)(Ol_g + off1) = lo;
    }
}

// ---------------------------------------------------------------------------
extern "C" void kernel_launch(void* const* d_in, const int* in_sizes, int n_in,
                              void* d_out, int out_size)
{
    const float* hs  = (const float*)d_in[0];
    const int*   pos = (const int*)d_in[2];
    const float* Wq  = (const float*)d_in[3];
    const float* Wk  = (const float*)d_in[4];
    const float* Wv  = (const float*)d_in[5];
    const float* Wo  = (const float*)d_in[6];
    float* out = (float*)d_out;

    __nv_bfloat16 *hsh, *hsl, *ath, *atl, *woh, *wol;
    __nv_bfloat16 *qhh, *qll, *khh, *kll, *vhh, *vll;
    cudaGetSymbolAddress((void**)&hsh, g_hs_hi);  cudaGetSymbolAddress((void**)&hsl, g_hs_lo);
    cudaGetSymbolAddress((void**)&ath, g_att_hi); cudaGetSymbolAddress((void**)&atl, g_att_lo);
    cudaGetSymbolAddress((void**)&woh, g_Wo_hi);  cudaGetSymbolAddress((void**)&wol, g_Wo_lo);
    cudaGetSymbolAddress((void**)&qhh, g_Qh);     cudaGetSymbolAddress((void**)&qll, g_Ql);
    cudaGetSymbolAddress((void**)&khh, g_Kh);     cudaGetSymbolAddress((void**)&kll, g_Kl);
    cudaGetSymbolAddress((void**)&vhh, g_Vh);     cudaGetSymbolAddress((void**)&vll, g_Vl);

    const int gemm_smem = 1024 + 2 * BUFB;
    cudaFuncSetAttribute(gemm_qkv, cudaFuncAttributeMaxDynamicSharedMemorySize, gemm_smem);
    cudaFuncSetAttribute(gemm_bf16x3, cudaFuncAttributeMaxDynamicSharedMemorySize, gemm_smem);
    cudaFuncSetAttribute(attn_mma, cudaFuncAttributeMaxDynamicSharedMemorySize, ATT_SMEM);

    // single fused split of all fp32 inputs
    split_all<<<(TOT4 + 255) / 256, 256>>>(hs, Wq, Wk, Wv, Wo);

    // fused QKV projection + RoPE + split
    gemm_qkv<<<dim3(48, 16), 256, gemm_smem>>>(hsh, hsl, pos,
                                               qhh, qll, khh, kll, vhh, vll);

    // attention (tensor cores), writes bf16 hi/lo directly
    attn_mma<<<dim3(S_LEN / 128, NH), 256, ATT_SMEM>>>(qhh, qll, khh, kll, vhh, vll, ath, atl);

    // output projection
    gemm_bf16x3<<<dim3(HID / 128, S_LEN / 128), 256, gemm_smem>>>(ath, atl, woh, wol, out, S_LEN, HID, KDIM);
}

// round 10
// speedup vs baseline: 1.5164x; 1.5164x over previous
#include <cuda_runtime.h>
#include <cuda_bf16.h>
#include <math.h>
#include <stdint.h>

#define S_LEN 2048
#define HID   4096
#define NH    32
#define NKV   8
#define HDIM  128
#define WINDOW 1024
#define KDIM  4096
#define NKVD  (NKV * HDIM)      // 1024

// ---------------- scratch (__device__ globals; no allocation) ----------------
__device__ __align__(256) __nv_bfloat16 g_hs_hi[S_LEN * HID];
__device__ __align__(256) __nv_bfloat16 g_hs_lo[S_LEN * HID];
__device__ __align__(256) __nv_bfloat16 g_att_hi[S_LEN * HID];
__device__ __align__(256) __nv_bfloat16 g_att_lo[S_LEN * HID];
__device__ __align__(256) __nv_bfloat16 g_Qh[S_LEN * HID];
__device__ __align__(256) __nv_bfloat16 g_Ql[S_LEN * HID];
__device__ __align__(256) __nv_bfloat16 g_Kh[S_LEN * NKVD];
__device__ __align__(256) __nv_bfloat16 g_Kl[S_LEN * NKVD];
__device__ __align__(256) __nv_bfloat16 g_Vh[S_LEN * NKVD];
__device__ __align__(256) __nv_bfloat16 g_Vl[S_LEN * NKVD];
__device__ __align__(256) __nv_bfloat16 g_Wq_hi[HID * HID];
__device__ __align__(256) __nv_bfloat16 g_Wq_lo[HID * HID];
__device__ __align__(256) __nv_bfloat16 g_Wk_hi[NKVD * HID];
__device__ __align__(256) __nv_bfloat16 g_Wk_lo[NKVD * HID];
__device__ __align__(256) __nv_bfloat16 g_Wv_hi[NKVD * HID];
__device__ __align__(256) __nv_bfloat16 g_Wv_lo[NKVD * HID];
__device__ __align__(256) __nv_bfloat16 g_Wo_hi[HID * HID];
__device__ __align__(256) __nv_bfloat16 g_Wo_lo[HID * HID];

// ---------------- helpers ----------------
__device__ __forceinline__ uint32_t smem_u32(const void* p) {
    uint32_t a;
    asm("{ .reg .u64 t; cvta.to.shared.u64 t, %1; cvt.u32.u64 %0, t; }" : "=r"(a) : "l"(p));
    return a;
}
__device__ __forceinline__ void cp16(uint32_t dst, const void* src) {
    asm volatile("cp.async.cg.shared.global [%0], [%1], 16;" :: "r"(dst), "l"(src));
}
__device__ __forceinline__ void cp_commit() {
    asm volatile("cp.async.commit_group;" ::: "memory");
}
template <int N>
__device__ __forceinline__ void cp_wait() {
    asm volatile("cp.async.wait_group %0;" :: "n"(N) : "memory");
}
__device__ __forceinline__ void ldsm_x4(uint32_t* r, uint32_t addr) {
    asm volatile("ldmatrix.sync.aligned.m8n8.x4.shared.b16 {%0,%1,%2,%3}, [%4];"
                 : "=r"(r[0]), "=r"(r[1]), "=r"(r[2]), "=r"(r[3]) : "r"(addr));
}
__device__ __forceinline__ void ldsm_x4_t(uint32_t* r, uint32_t addr) {
    asm volatile("ldmatrix.sync.aligned.m8n8.x4.trans.shared.b16 {%0,%1,%2,%3}, [%4];"
                 : "=r"(r[0]), "=r"(r[1]), "=r"(r[2]), "=r"(r[3]) : "r"(addr));
}
__device__ __forceinline__ void mma16816(float* c, const uint32_t* a,
                                         uint32_t b0, uint32_t b1) {
    asm volatile(
        "mma.sync.aligned.m16n8k16.row.col.f32.bf16.bf16.f32 "
        "{%0,%1,%2,%3}, {%4,%5,%6,%7}, {%8,%9}, {%0,%1,%2,%3};"
        : "+f"(c[0]), "+f"(c[1]), "+f"(c[2]), "+f"(c[3])
        : "r"(a[0]), "r"(a[1]), "r"(a[2]), "r"(a[3]), "r"(b0), "r"(b1));
}
__device__ __forceinline__ void packsplit(float x, float y, uint32_t& hi, uint32_t& lo) {
    __nv_bfloat16 hx = __float2bfloat16(x), hy = __float2bfloat16(y);
    __nv_bfloat16 lx = __float2bfloat16(x - __bfloat162float(hx));
    __nv_bfloat16 ly = __float2bfloat16(y - __bfloat162float(hy));
    hi = (uint32_t)__bfloat16_as_ushort(hx) | ((uint32_t)__bfloat16_as_ushort(hy) << 16);
    lo = (uint32_t)__bfloat16_as_ushort(lx) | ((uint32_t)__bfloat16_as_ushort(ly) << 16);
}

#define SWZ(off) ((off) ^ (((off) >> 3) & 0x70))

// ---------------------------------------------------------------------------
// fused split of all fp32 inputs -> bf16 hi + lo (single launch)
// ---------------------------------------------------------------------------
#define HS4 (S_LEN * HID / 4)
#define WQ4 (HID * HID / 4)
#define WK4 (NKVD * HID / 4)
#define WV4 (NKVD * HID / 4)
#define WO4 (HID * HID / 4)
#define TOT4 (HS4 + WQ4 + WK4 + WV4 + WO4)

__global__ void split_all(const float* __restrict__ hs, const float* __restrict__ Wq,
                          const float* __restrict__ Wk, const float* __restrict__ Wv,
                          const float* __restrict__ Wo)
{
    int i = blockIdx.x * blockDim.x + threadIdx.x;
    if (i >= TOT4) return;
    const float* in;
    __nv_bfloat16 *ho, *lo;
    int off;
    if (i < HS4)                         { in = hs; ho = g_hs_hi; lo = g_hs_lo; off = i; }
    else if (i < HS4 + WQ4)              { in = Wq; ho = g_Wq_hi; lo = g_Wq_lo; off = i - HS4; }
    else if (i < HS4 + WQ4 + WK4)        { in = Wk; ho = g_Wk_hi; lo = g_Wk_lo; off = i - HS4 - WQ4; }
    else if (i < HS4 + WQ4 + WK4 + WV4)  { in = Wv; ho = g_Wv_hi; lo = g_Wv_lo; off = i - HS4 - WQ4 - WK4; }
    else                                 { in = Wo; ho = g_Wo_hi; lo = g_Wo_lo; off = i - HS4 - WQ4 - WK4 - WV4; }

    float4 v = ((const float4*)in)[off];
    float x[4] = {v.x, v.y, v.z, v.w};
    unsigned short h[4], l[4];
    #pragma unroll
    for (int j = 0; j < 4; ++j) {
        __nv_bfloat16 hb = __float2bfloat16(x[j]);
        __nv_bfloat16 lb = __float2bfloat16(x[j] - __bfloat162float(hb));
        h[j] = __bfloat16_as_ushort(hb);
        l[j] = __bfloat16_as_ushort(lb);
    }
    ((ushort4*)ho)[off] = make_ushort4(h[0], h[1], h[2], h[3]);
    ((ushort4*)lo)[off] = make_ushort4(l[0], l[1], l[2], l[3]);
}

// ---------------------------------------------------------------------------
// GEMM constants: 3-stage cp.async pipeline (depth-2 prefetch, 1 barrier/chunk)
// ---------------------------------------------------------------------------
#define GK 64
#define TILEB 16384
#define BUFB (4 * TILEB)        // 64 KB per stage
#define NSTAGE 3
#define GEMM_SMEM (1024 + NSTAGE * BUFB)

// compute body shared by both GEMM kernels
#define GEMM_COMPUTE(bufb)                                                        \
    _Pragma("unroll")                                                             \
    for (int ks = 0; ks < 4; ++ks) {                                              \
        uint32_t ah[4][4], al[4][4], bh[2][4], bl[2][4];                          \
        _Pragma("unroll")                                                         \
        for (int mi = 0; mi < 4; ++mi) {                                          \
            uint32_t off = (uint32_t)((wr * 64 + mi * 16 + lrow) * 128 + ks * 32 + lkb); \
            uint32_t sw = SWZ(off);                                               \
            ldsm_x4(ah[mi], (bufb) + sw);                                         \
            ldsm_x4(al[mi], (bufb) + TILEB + sw);                                 \
        }                                                                         \
        _Pragma("unroll")                                                         \
        for (int np = 0; np < 2; ++np) {                                          \
            uint32_t off = (uint32_t)((wc * 32 + np * 16 + lrow) * 128 + ks * 32 + lkb); \
            uint32_t sw = SWZ(off);                                               \
            ldsm_x4(bh[np], (bufb) + 2 * TILEB + sw);                             \
            ldsm_x4(bl[np], (bufb) + 3 * TILEB + sw);                             \
        }                                                                         \
        _Pragma("unroll")                                                         \
        for (int mi = 0; mi < 4; ++mi)                                            \
            _Pragma("unroll")                                                     \
            for (int ni = 0; ni < 4; ++ni) {                                      \
                uint32_t b0h = bh[ni >> 1][ni & 1], b1h = bh[ni >> 1][2 + (ni & 1)]; \
                uint32_t b0l = bl[ni >> 1][ni & 1], b1l = bl[ni >> 1][2 + (ni & 1)]; \
                mma16816(acc[mi][ni], ah[mi], b0h, b1h);                          \
                mma16816(acc[mi][ni], ah[mi], b0l, b1l);                          \
                mma16816(acc[mi][ni], al[mi], b0h, b1h);                          \
            }                                                                     \
    }

// ---------------------------------------------------------------------------
// Fused QKV projection + RoPE + hi/lo split. Logical N = 6144, grid (48, 16).
// ---------------------------------------------------------------------------
__global__ void __launch_bounds__(256, 1)
gemm_qkv(const __nv_bfloat16* __restrict__ Ahi, const __nv_bfloat16* __restrict__ Alo,
         const int* __restrict__ pos,
         __nv_bfloat16* __restrict__ Qh, __nv_bfloat16* __restrict__ Ql,
         __nv_bfloat16* __restrict__ Kh, __nv_bfloat16* __restrict__ Kl,
         __nv_bfloat16* __restrict__ Vh, __nv_bfloat16* __restrict__ Vl)
{
    extern __shared__ char smraw[];
    char* smc = (char*)(((uintptr_t)smraw + 1023) & ~(uintptr_t)1023);
    const uint32_t sbase = smem_u32(smc);

    const int tid = threadIdx.x;
    const int lane = tid & 31;
    const int wid = tid >> 5;
    const int wr = wid >> 2;
    const int wc = wid & 3;
    const int bx = blockIdx.x;
    const int m0 = blockIdx.y * 128;

    const __nv_bfloat16 *Bhi, *Blo;
    int bn0;
    if (bx < 32)      { Bhi = g_Wq_hi; Blo = g_Wq_lo; bn0 = bx * 128; }
    else if (bx < 40) { Bhi = g_Wk_hi; Blo = g_Wk_lo; bn0 = (bx - 32) * 128; }
    else              { Bhi = g_Wv_hi; Blo = g_Wv_lo; bn0 = (bx - 40) * 128; }

    float acc[4][4][4];
    #pragma unroll
    for (int a = 0; a < 4; ++a)
        #pragma unroll
        for (int b = 0; b < 4; ++b)
            #pragma unroll
            for (int c = 0; c < 4; ++c) acc[a][b][c] = 0.f;

    const int NCHUNK = KDIM / GK;

    auto load_chunk = [&](int it) {
        const uint32_t bufb = sbase + (it % NSTAGE) * BUFB;
        const int k0 = it * GK;
        #pragma unroll
        for (int p = 0; p < 4; ++p) {
            int linear = tid + p * 256;
            int r = linear >> 3;
            int cb = (linear & 7) * 16;
            uint32_t sw = SWZ((uint32_t)(r * 128 + cb));
            size_t ga = (size_t)(m0 + r) * KDIM + k0 + (cb >> 1);
            size_t gb = (size_t)(bn0 + r) * KDIM + k0 + (cb >> 1);
            cp16(bufb + sw,              &Ahi[ga]);
            cp16(bufb + TILEB + sw,      &Alo[ga]);
            cp16(bufb + 2 * TILEB + sw,  &Bhi[gb]);
            cp16(bufb + 3 * TILEB + sw,  &Blo[gb]);
        }
    };

    load_chunk(0); cp_commit();
    load_chunk(1); cp_commit();

    const int lrow = lane & 15;
    const int lkb  = (lane >> 4) * 16;

    for (int it = 0; it < NCHUNK; ++it) {
        cp_wait<1>();          // chunk `it` landed; `it+1` may still stream
        __syncthreads();       // all warps: prev compute done + chunk visible
        if (it + 2 < NCHUNK) load_chunk(it + 2);
        cp_commit();           // always commit (possibly empty) to keep counts
        const uint32_t bufb = sbase + (it % NSTAGE) * BUFB;
        GEMM_COMPUTE(bufb)
    }

    __syncthreads();   // mainloop smem reads done before Cs reuse

    // ---- epilogue: stage acc in smem, RoPE (Q/K) + split, store bf16 hi/lo ----
    float* Cs = (float*)smc;
    {
        const int rb = wr * 64 + (lane >> 2);
        const int cb2 = wc * 32 + (lane & 3) * 2;
        #pragma unroll
        for (int mi = 0; mi < 4; ++mi)
            #pragma unroll
            for (int ni = 0; ni < 4; ++ni) {
                int r = rb + mi * 16, cc = cb2 + ni * 8;
                Cs[r * 132 + cc]           = acc[mi][ni][0];
                Cs[r * 132 + cc + 1]       = acc[mi][ni][1];
                Cs[(r + 8) * 132 + cc]     = acc[mi][ni][2];
                Cs[(r + 8) * 132 + cc + 1] = acc[mi][ni][3];
            }
    }
    __syncthreads();

    __nv_bfloat16 *Hout, *Lout;
    int stride, off;
    bool dorope;
    if (bx < 32)      { Hout = Qh; Lout = Ql; stride = HID;  off = bx * 128;        dorope = true; }
    else if (bx < 40) { Hout = Kh; Lout = Kl; stride = NKVD; off = (bx - 32) * 128; dorope = true; }
    else              { Hout = Vh; Lout = Vl; stride = NKVD; off = (bx - 40) * 128; dorope = false; }

    const int d0 = tid & 63;
    const int rg = tid >> 6;
    const float invf = dorope ? expf(-(float)d0 * 0.14391156831212787f) : 0.f;

    #pragma unroll 4
    for (int rr = 0; rr < 32; ++rr) {
        const int r = rg * 32 + rr;
        const int t = m0 + r;
        float x0 = Cs[r * 132 + d0];
        float x1 = Cs[r * 132 + d0 + 64];
        float y0, y1;
        if (dorope) {
            float s, c;
            sincosf((float)pos[t] * invf, &s, &c);
            y0 = x0 * c - x1 * s;
            y1 = x1 * c + x0 * s;
        } else {
            y0 = x0; y1 = x1;
        }
        __nv_bfloat16 h0 = __float2bfloat16(y0);
        __nv_bfloat16 l0 = __float2bfloat16(y0 - __bfloat162float(h0));
        __nv_bfloat16 h1 = __float2bfloat16(y1);
        __nv_bfloat16 l1 = __float2bfloat16(y1 - __bfloat162float(h1));
        size_t o = (size_t)t * stride + off + d0;
        Hout[o]      = h0;
        Lout[o]      = l0;
        Hout[o + 64] = h1;
        Lout[o + 64] = l1;
    }
}

// ---------------------------------------------------------------------------
// Generic GEMM (Wo projection): C = (Ahi+Alo)*(Bhi+Blo)^T, fp32 out.
// ---------------------------------------------------------------------------
__global__ void __launch_bounds__(256, 1)
gemm_bf16x3(const __nv_bfloat16* __restrict__ Ahi, const __nv_bfloat16* __restrict__ Alo,
            const __nv_bfloat16* __restrict__ Bhi, const __nv_bfloat16* __restrict__ Blo,
            float* __restrict__ C, int M, int N, int K)
{
    extern __shared__ char smraw[];
    char* smc = (char*)(((uintptr_t)smraw + 1023) & ~(uintptr_t)1023);
    const uint32_t sbase = smem_u32(smc);

    const int tid = threadIdx.x;
    const int lane = tid & 31;
    const int wid = tid >> 5;
    const int wr = wid >> 2;
    const int wc = wid & 3;
    const int m0 = blockIdx.y * 128;
    const int n0 = blockIdx.x * 128;

    float acc[4][4][4];
    #pragma unroll
    for (int a = 0; a < 4; ++a)
        #pragma unroll
        for (int b = 0; b < 4; ++b)
            #pragma unroll
            for (int c = 0; c < 4; ++c) acc[a][b][c] = 0.f;

    const int NCHUNK = K / GK;

    auto load_chunk = [&](int it) {
        const uint32_t bufb = sbase + (it % NSTAGE) * BUFB;
        const int k0 = it * GK;
        #pragma unroll
        for (int p = 0; p < 4; ++p) {
            int linear = tid + p * 256;
            int r = linear >> 3;
            int cb = (linear & 7) * 16;
            uint32_t sw = SWZ((uint32_t)(r * 128 + cb));
            size_t ga = (size_t)(m0 + r) * K + k0 + (cb >> 1);
            size_t gb = (size_t)(n0 + r) * K + k0 + (cb >> 1);
            cp16(bufb + sw,              &Ahi[ga]);
            cp16(bufb + TILEB + sw,      &Alo[ga]);
            cp16(bufb + 2 * TILEB + sw,  &Bhi[gb]);
            cp16(bufb + 3 * TILEB + sw,  &Blo[gb]);
        }
    };

    load_chunk(0); cp_commit();
    load_chunk(1); cp_commit();

    const int lrow = lane & 15;
    const int lkb  = (lane >> 4) * 16;

    for (int it = 0; it < NCHUNK; ++it) {
        cp_wait<1>();
        __syncthreads();
        if (it + 2 < NCHUNK) load_chunk(it + 2);
        cp_commit();
        const uint32_t bufb = sbase + (it % NSTAGE) * BUFB;
        GEMM_COMPUTE(bufb)
    }

    const int row_base = m0 + wr * 64 + (lane >> 2);
    const int col_base = n0 + wc * 32 + (lane & 3) * 2;
    #pragma unroll
    for (int mi = 0; mi < 4; ++mi)
        #pragma unroll
        for (int ni = 0; ni < 4; ++ni) {
            int r = row_base + mi * 16;
            int cc = col_base + ni * 8;
            *(float2*)&C[(size_t)r * N + cc]       = make_float2(acc[mi][ni][0], acc[mi][ni][1]);
            *(float2*)&C[(size_t)(r + 8) * N + cc] = make_float2(acc[mi][ni][2], acc[mi][ni][3]);
        }
}

// ---------------------------------------------------------------------------
// Flash attention on tensor cores (bf16x3, online softmax in registers).
// R8-proven double-buffered KV pipeline.
// ---------------------------------------------------------------------------
#define ATT_SMEM (1024 + 3 * 65536)

__global__ void __launch_bounds__(256)
attn_mma(const __nv_bfloat16* __restrict__ Qh_g, const __nv_bfloat16* __restrict__ Ql_g,
         const __nv_bfloat16* __restrict__ Kh_g, const __nv_bfloat16* __restrict__ Kl_g,
         const __nv_bfloat16* __restrict__ Vh_g, const __nv_bfloat16* __restrict__ Vl_g,
         __nv_bfloat16* __restrict__ Oh_g, __nv_bfloat16* __restrict__ Ol_g)
{
    extern __shared__ char smraw[];
    char* smc = (char*)(((uintptr_t)smraw + 1023) & ~(uintptr_t)1023);
    const uint32_t qbase = smem_u32(smc);
    const uint32_t kvbase = qbase + 65536;

    const int tid = threadIdx.x;
    const int lane = tid & 31;
    const int w = tid >> 5;
    const int wm = w * 16;
    const int m0 = blockIdx.x * 128;
    const int h = blockIdx.y;
    const int kvh = h >> 2;
    const int lrow = lane & 15;
    const int lhi = (lane >> 4) * 16;

    auto load_q = [&]() {
        #pragma unroll
        for (int p = 0; p < 16; ++p) {
            int lin = tid + p * 256;
            int t2 = lin >> 11;
            int rem = lin & 2047;
            int row = rem >> 4;
            int c = rem & 15;
            int half = c >> 3;
            int cb = (c & 7) * 16;
            uint32_t dst = qbase + t2 * 32768 + half * 16384
                         + SWZ((uint32_t)(row * 128 + cb));
            size_t elem = (size_t)(m0 + row) * HID + h * HDIM + half * 64 + (c & 7) * 8;
            cp16(dst, (t2 ? Ql_g : Qh_g) + elem);
        }
    };
    auto load_kv = [&](int j, int b) {
        const uint32_t base = kvbase + b * 65536;
        #pragma unroll
        for (int p = 0; p < 16; ++p) {
            int lin = tid + p * 256;
            int t4 = lin >> 10;
            int rem = lin & 1023;
            int row = rem >> 4;
            int c = rem & 15;
            int half = c >> 3;
            int cb = (c & 7) * 16;
            uint32_t dst = base + t4 * 16384 + half * 8192
                         + SWZ((uint32_t)(row * 128 + cb));
            size_t elem = (size_t)(j * 64 + row) * NKVD + kvh * HDIM
                        + half * 64 + (c & 7) * 8;
            const __nv_bfloat16* src =
                (t4 < 2) ? ((t4 & 1) ? Kl_g : Kh_g) : ((t4 & 1) ? Vl_g : Vh_g);
            cp16(dst, src + elem);
        }
    };

    const int j0 = (m0 >= 1024) ? (m0 - 1023) / 64 : 0;
    const int jend = m0 / 64 + 1;

    load_q();
    load_kv(j0, 0);
    cp_commit();

    float o[16][4];
    #pragma unroll
    for (int i = 0; i < 16; ++i)
        #pragma unroll
        for (int c = 0; c < 4; ++c) o[i][c] = 0.f;
    float mst0 = -INFINITY, mst1 = -INFINITY, lst0 = 0.f, lst1 = 0.f;

    const int row0 = m0 + wm + (lane >> 2);
    const int row1 = row0 + 8;
    const float scale = 0.08838834764831845f;

    for (int j = j0; j <= jend; ++j) {
        const int b = (j - j0) & 1;
        if (j + 1 <= jend) {
            load_kv(j + 1, b ^ 1);
            cp_commit();
            cp_wait<1>();
        } else {
            cp_wait<0>();
        }
        __syncthreads();

        const uint32_t kvb = kvbase + b * 65536;

        float sf[8][4];
        #pragma unroll
        for (int i = 0; i < 8; ++i)
            #pragma unroll
            for (int c = 0; c < 4; ++c) sf[i][c] = 0.f;

        #pragma unroll
        for (int kd = 0; kd < 8; ++kd) {
            const int half = kd >> 2;
            const uint32_t koff = (uint32_t)((kd & 3) * 32 + lhi);
            uint32_t ah[4], al[4], bh[4][4], bl[4][4];
            {
                uint32_t sw = SWZ((uint32_t)((wm + lrow) * 128) + koff);
                ldsm_x4(ah, qbase + half * 16384 + sw);
                ldsm_x4(al, qbase + 32768 + half * 16384 + sw);
            }
            #pragma unroll
            for (int nb = 0; nb < 4; ++nb) {
                uint32_t sw = SWZ((uint32_t)((nb * 16 + lrow) * 128) + koff);
                ldsm_x4(bh[nb], kvb + half * 8192 + sw);
                ldsm_x4(bl[nb], kvb + 16384 + half * 8192 + sw);
            }
            #pragma unroll
            for (int ni = 0; ni < 8; ++ni) {
                const int nb = ni >> 1, s = ni & 1;
                mma16816(sf[ni], ah, bh[nb][s], bh[nb][s + 2]);
                mma16816(sf[ni], ah, bl[nb][s], bl[nb][s + 2]);
                mma16816(sf[ni], al, bh[nb][s], bh[nb][s + 2]);
            }
        }

        const int colb = j * 64 + (lane & 3) * 2;
        float rmax0 = -INFINITY, rmax1 = -INFINITY;
        #pragma unroll
        for (int ni = 0; ni < 8; ++ni) {
            int c0 = colb + ni * 8, c1 = c0 + 1;
            sf[ni][0] = (c0 <= row0 && row0 - c0 < WINDOW) ? sf[ni][0] * scale : -INFINITY;
            sf[ni][1] = (c1 <= row0 && row0 - c1 < WINDOW) ? sf[ni][1] * scale : -INFINITY;
            sf[ni][2] = (c0 <= row1 && row1 - c0 < WINDOW) ? sf[ni][2] * scale : -INFINITY;
            sf[ni][3] = (c1 <= row1 && row1 - c1 < WINDOW) ? sf[ni][3] * scale : -INFINITY;
            rmax0 = fmaxf(rmax0, fmaxf(sf[ni][0], sf[ni][1]));
            rmax1 = fmaxf(rmax1, fmaxf(sf[ni][2], sf[ni][3]));
        }
        rmax0 = fmaxf(rmax0, __shfl_xor_sync(0xffffffffu, rmax0, 1));
        rmax0 = fmaxf(rmax0, __shfl_xor_sync(0xffffffffu, rmax0, 2));
        rmax1 = fmaxf(rmax1, __shfl_xor_sync(0xffffffffu, rmax1, 1));
        rmax1 = fmaxf(rmax1, __shfl_xor_sync(0xffffffffu, rmax1, 2));

        float mn0 = fmaxf(mst0, rmax0), mn1 = fmaxf(mst1, rmax1);
        float mc0 = fmaxf(mn0, -1e30f), mc1 = fmaxf(mn1, -1e30f);
        float a0 = __expf(fmaxf(mst0, -1e30f) - mc0);
        float a1 = __expf(fmaxf(mst1, -1e30f) - mc1);
        float sum0 = 0.f, sum1 = 0.f;
        #pragma unroll
        for (int ni = 0; ni < 8; ++ni) {
            sf[ni][0] = __expf(sf[ni][0] - mc0);
            sf[ni][1] = __expf(sf[ni][1] - mc0);
            sf[ni][2] = __expf(sf[ni][2] - mc1);
            sf[ni][3] = __expf(sf[ni][3] - mc1);
            sum0 += sf[ni][0] + sf[ni][1];
            sum1 += sf[ni][2] + sf[ni][3];
        }
        sum0 += __shfl_xor_sync(0xffffffffu, sum0, 1);
        sum0 += __shfl_xor_sync(0xffffffffu, sum0, 2);
        sum1 += __shfl_xor_sync(0xffffffffu, sum1, 1);
        sum1 += __shfl_xor_sync(0xffffffffu, sum1, 2);
        mst0 = mn0; mst1 = mn1;
        lst0 = lst0 * a0 + sum0;
        lst1 = lst1 * a1 + sum1;
        #pragma unroll
        for (int nf = 0; nf < 16; ++nf) {
            o[nf][0] *= a0; o[nf][1] *= a0;
            o[nf][2] *= a1; o[nf][3] *= a1;
        }

        #pragma unroll
        for (int ks = 0; ks < 4; ++ks) {
            uint32_t ah[4], al[4];
            packsplit(sf[2 * ks][0],     sf[2 * ks][1],     ah[0], al[0]);
            packsplit(sf[2 * ks][2],     sf[2 * ks][3],     ah[1], al[1]);
            packsplit(sf[2 * ks + 1][0], sf[2 * ks + 1][1], ah[2], al[2]);
            packsplit(sf[2 * ks + 1][2], sf[2 * ks + 1][3], ah[3], al[3]);
            #pragma unroll
            for (int g = 0; g < 8; ++g) {
                const int half = g >> 2;
                uint32_t off = SWZ((uint32_t)((ks * 16 + lrow) * 128 + (g & 3) * 32) + lhi);
                uint32_t vh[4], vl[4];
                ldsm_x4_t(vh, kvb + 32768 + half * 8192 + off);
                ldsm_x4_t(vl, kvb + 49152 + half * 8192 + off);
                mma16816(o[2 * g],     ah, vh[0], vh[1]);
                mma16816(o[2 * g],     ah, vl[0], vl[1]);
                mma16816(o[2 * g],     al, vh[0], vh[1]);
                mma16816(o[2 * g + 1], ah, vh[2], vh[3]);
                mma16816(o[2 * g + 1], ah, vl[2], vl[3]);
                mma16816(o[2 * g + 1], al, vh[2], vh[3]);
            }
        }
        __syncthreads();
    }

    const float inv0 = 1.f / lst0;
    const float inv1 = 1.f / lst1;
    #pragma unroll
    for (int nf = 0; nf < 16; ++nf) {
        int d = h * HDIM + nf * 8 + (lane & 3) * 2;
        size_t off0 = (size_t)row0 * HID + d;
        size_t off1 = (size_t)row1 * HID + d;
        uint32_t hi, lo;
        packsplit(o[nf][0] * inv0, o[nf][1] * inv0, hi, lo);
        *(uint32_t*)(Oh_g + off0) = hi;
        *(uint32_t*)(Ol_g + off0) = lo;
        packsplit(o[nf][2] * inv1, o[nf][3] * inv1, hi, lo);
        *(uint32_t*)(Oh_g + off1) = hi;
        *(uint32_t*)(Ol_g + off1) = lo;
    }
}

// ---------------------------------------------------------------------------
extern "C" void kernel_launch(void* const* d_in, const int* in_sizes, int n_in,
                              void* d_out, int out_size)
{
    const float* hs  = (const float*)d_in[0];
    const int*   pos = (const int*)d_in[2];
    const float* Wq  = (const float*)d_in[3];
    const float* Wk  = (const float*)d_in[4];
    const float* Wv  = (const float*)d_in[5];
    const float* Wo  = (const float*)d_in[6];
    float* out = (float*)d_out;

    __nv_bfloat16 *hsh, *hsl, *ath, *atl, *woh, *wol;
    __nv_bfloat16 *qhh, *qll, *khh, *kll, *vhh, *vll;
    cudaGetSymbolAddress((void**)&hsh, g_hs_hi);  cudaGetSymbolAddress((void**)&hsl, g_hs_lo);
    cudaGetSymbolAddress((void**)&ath, g_att_hi); cudaGetSymbolAddress((void**)&atl, g_att_lo);
    cudaGetSymbolAddress((void**)&woh, g_Wo_hi);  cudaGetSymbolAddress((void**)&wol, g_Wo_lo);
    cudaGetSymbolAddress((void**)&qhh, g_Qh);     cudaGetSymbolAddress((void**)&qll, g_Ql);
    cudaGetSymbolAddress((void**)&khh, g_Kh);     cudaGetSymbolAddress((void**)&kll, g_Kl);
    cudaGetSymbolAddress((void**)&vhh, g_Vh);     cudaGetSymbolAddress((void**)&vll, g_Vl);

    cudaFuncSetAttribute(gemm_qkv, cudaFuncAttributeMaxDynamicSharedMemorySize, GEMM_SMEM);
    cudaFuncSetAttribute(gemm_bf16x3, cudaFuncAttributeMaxDynamicSharedMemorySize, GEMM_SMEM);
    cudaFuncSetAttribute(attn_mma, cudaFuncAttributeMaxDynamicSharedMemorySize, ATT_SMEM);

    // single fused split of all fp32 inputs
    split_all<<<(TOT4 + 255) / 256, 256>>>(hs, Wq, Wk, Wv, Wo);

    // fused QKV projection + RoPE + split
    gemm_qkv<<<dim3(48, 16), 256, GEMM_SMEM>>>(hsh, hsl, pos,
                                               qhh, qll, khh, kll, vhh, vll);

    // attention (tensor cores), writes bf16 hi/lo directly
    attn_mma<<<dim3(S_LEN / 128, NH), 256, ATT_SMEM>>>(qhh, qll, khh, kll, vhh, vll, ath, atl);

    // output projection
    gemm_bf16x3<<<dim3(HID / 128, S_LEN / 128), 256, GEMM_SMEM>>>(ath, atl, woh, wol, out, S_LEN, HID, KDIM);
}

// round 11
// speedup vs baseline: 1.5689x; 1.0346x over previous
#include <cuda_runtime.h>
#include <cuda_bf16.h>
#include <math.h>
#include <stdint.h>

#define S_LEN 2048
#define HID   4096
#define NH    32
#define NKV   8
#define HDIM  128
#define WINDOW 1024
#define KDIM  4096
#define NKVD  (NKV * HDIM)      // 1024

// ---------------- scratch (__device__ globals; no allocation) ----------------
__device__ __align__(256) __nv_bfloat16 g_hs_hi[S_LEN * HID];
__device__ __align__(256) __nv_bfloat16 g_hs_lo[S_LEN * HID];
__device__ __align__(256) __nv_bfloat16 g_att_hi[S_LEN * HID];
__device__ __align__(256) __nv_bfloat16 g_att_lo[S_LEN * HID];
__device__ __align__(256) __nv_bfloat16 g_Qh[S_LEN * HID];
__device__ __align__(256) __nv_bfloat16 g_Ql[S_LEN * HID];
__device__ __align__(256) __nv_bfloat16 g_Kh[S_LEN * NKVD];
__device__ __align__(256) __nv_bfloat16 g_Kl[S_LEN * NKVD];
__device__ __align__(256) __nv_bfloat16 g_Vh[S_LEN * NKVD];
__device__ __align__(256) __nv_bfloat16 g_Vl[S_LEN * NKVD];
__device__ __align__(256) __nv_bfloat16 g_Wq_hi[HID * HID];
__device__ __align__(256) __nv_bfloat16 g_Wq_lo[HID * HID];
__device__ __align__(256) __nv_bfloat16 g_Wk_hi[NKVD * HID];
__device__ __align__(256) __nv_bfloat16 g_Wk_lo[NKVD * HID];
__device__ __align__(256) __nv_bfloat16 g_Wv_hi[NKVD * HID];
__device__ __align__(256) __nv_bfloat16 g_Wv_lo[NKVD * HID];
__device__ __align__(256) __nv_bfloat16 g_Wo_hi[HID * HID];
__device__ __align__(256) __nv_bfloat16 g_Wo_lo[HID * HID];

// ---------------- helpers ----------------
__device__ __forceinline__ uint32_t smem_u32(const void* p) {
    uint32_t a;
    asm("{ .reg .u64 t; cvta.to.shared.u64 t, %1; cvt.u32.u64 %0, t; }" : "=r"(a) : "l"(p));
    return a;
}
__device__ __forceinline__ void cp16(uint32_t dst, const void* src) {
    asm volatile("cp.async.cg.shared.global [%0], [%1], 16;" :: "r"(dst), "l"(src));
}
__device__ __forceinline__ void cp_commit() {
    asm volatile("cp.async.commit_group;" ::: "memory");
}
template <int N>
__device__ __forceinline__ void cp_wait() {
    asm volatile("cp.async.wait_group %0;" :: "n"(N) : "memory");
}
__device__ __forceinline__ void ldsm_x4(uint32_t* r, uint32_t addr) {
    asm volatile("ldmatrix.sync.aligned.m8n8.x4.shared.b16 {%0,%1,%2,%3}, [%4];"
                 : "=r"(r[0]), "=r"(r[1]), "=r"(r[2]), "=r"(r[3]) : "r"(addr));
}
__device__ __forceinline__ void ldsm_x4_t(uint32_t* r, uint32_t addr) {
    asm volatile("ldmatrix.sync.aligned.m8n8.x4.trans.shared.b16 {%0,%1,%2,%3}, [%4];"
                 : "=r"(r[0]), "=r"(r[1]), "=r"(r[2]), "=r"(r[3]) : "r"(addr));
}
__device__ __forceinline__ void mma16816(float* c, const uint32_t* a,
                                         uint32_t b0, uint32_t b1) {
    asm volatile(
        "mma.sync.aligned.m16n8k16.row.col.f32.bf16.bf16.f32 "
        "{%0,%1,%2,%3}, {%4,%5,%6,%7}, {%8,%9}, {%0,%1,%2,%3};"
        : "+f"(c[0]), "+f"(c[1]), "+f"(c[2]), "+f"(c[3])
        : "r"(a[0]), "r"(a[1]), "r"(a[2]), "r"(a[3]), "r"(b0), "r"(b1));
}
__device__ __forceinline__ void packsplit(float x, float y, uint32_t& hi, uint32_t& lo) {
    __nv_bfloat16 hx = __float2bfloat16(x), hy = __float2bfloat16(y);
    __nv_bfloat16 lx = __float2bfloat16(x - __bfloat162float(hx));
    __nv_bfloat16 ly = __float2bfloat16(y - __bfloat162float(hy));
    hi = (uint32_t)__bfloat16_as_ushort(hx) | ((uint32_t)__bfloat16_as_ushort(hy) << 16);
    lo = (uint32_t)__bfloat16_as_ushort(lx) | ((uint32_t)__bfloat16_as_ushort(ly) << 16);
}

#define SWZ(off) ((off) ^ (((off) >> 3) & 0x70))

// ---------------------------------------------------------------------------
// fused split of all fp32 inputs -> bf16 hi + lo (single launch)
// ---------------------------------------------------------------------------
#define HS4 (S_LEN * HID / 4)
#define WQ4 (HID * HID / 4)
#define WK4 (NKVD * HID / 4)
#define WV4 (NKVD * HID / 4)
#define WO4 (HID * HID / 4)
#define TOT4 (HS4 + WQ4 + WK4 + WV4 + WO4)

__global__ void split_all(const float* __restrict__ hs, const float* __restrict__ Wq,
                          const float* __restrict__ Wk, const float* __restrict__ Wv,
                          const float* __restrict__ Wo)
{
    int i = blockIdx.x * blockDim.x + threadIdx.x;
    if (i >= TOT4) return;
    const float* in;
    __nv_bfloat16 *ho, *lo;
    int off;
    if (i < HS4)                         { in = hs; ho = g_hs_hi; lo = g_hs_lo; off = i; }
    else if (i < HS4 + WQ4)              { in = Wq; ho = g_Wq_hi; lo = g_Wq_lo; off = i - HS4; }
    else if (i < HS4 + WQ4 + WK4)        { in = Wk; ho = g_Wk_hi; lo = g_Wk_lo; off = i - HS4 - WQ4; }
    else if (i < HS4 + WQ4 + WK4 + WV4)  { in = Wv; ho = g_Wv_hi; lo = g_Wv_lo; off = i - HS4 - WQ4 - WK4; }
    else                                 { in = Wo; ho = g_Wo_hi; lo = g_Wo_lo; off = i - HS4 - WQ4 - WK4 - WV4; }

    float4 v = ((const float4*)in)[off];
    float x[4] = {v.x, v.y, v.z, v.w};
    unsigned short h[4], l[4];
    #pragma unroll
    for (int j = 0; j < 4; ++j) {
        __nv_bfloat16 hb = __float2bfloat16(x[j]);
        __nv_bfloat16 lb = __float2bfloat16(x[j] - __bfloat162float(hb));
        h[j] = __bfloat16_as_ushort(hb);
        l[j] = __bfloat16_as_ushort(lb);
    }
    ((ushort4*)ho)[off] = make_ushort4(h[0], h[1], h[2], h[3]);
    ((ushort4*)lo)[off] = make_ushort4(l[0], l[1], l[2], l[3]);
}

// ---------------------------------------------------------------------------
// GEMM: 512 threads (16 warps, 4/SMSP), warp tile 32x32, CTA tile 128x128.
// 3-stage cp.async pipeline, 1 barrier/chunk.
// ---------------------------------------------------------------------------
#define GK 64
#define TILEB 16384
#define BUFB (4 * TILEB)        // 64 KB per stage
#define NSTAGE 3
#define GEMM_SMEM (1024 + NSTAGE * BUFB)
#define NTHR 512

// compute body (warp tile 32x32): acc[2][4][4]
#define GEMM_COMPUTE(bufb)                                                        \
    _Pragma("unroll")                                                             \
    for (int ks = 0; ks < 4; ++ks) {                                              \
        uint32_t ah[2][4], al[2][4], bh[2][4], bl[2][4];                          \
        _Pragma("unroll")                                                         \
        for (int mi = 0; mi < 2; ++mi) {                                          \
            uint32_t off = (uint32_t)((wr * 32 + mi * 16 + lrow) * 128 + ks * 32 + lkb); \
            uint32_t sw = SWZ(off);                                               \
            ldsm_x4(ah[mi], (bufb) + sw);                                         \
            ldsm_x4(al[mi], (bufb) + TILEB + sw);                                 \
        }                                                                         \
        _Pragma("unroll")                                                         \
        for (int np = 0; np < 2; ++np) {                                          \
            uint32_t off = (uint32_t)((wc * 32 + np * 16 + lrow) * 128 + ks * 32 + lkb); \
            uint32_t sw = SWZ(off);                                               \
            ldsm_x4(bh[np], (bufb) + 2 * TILEB + sw);                             \
            ldsm_x4(bl[np], (bufb) + 3 * TILEB + sw);                             \
        }                                                                         \
        _Pragma("unroll")                                                         \
        for (int mi = 0; mi < 2; ++mi)                                            \
            _Pragma("unroll")                                                     \
            for (int ni = 0; ni < 4; ++ni) {                                      \
                uint32_t b0h = bh[ni >> 1][ni & 1], b1h = bh[ni >> 1][2 + (ni & 1)]; \
                uint32_t b0l = bl[ni >> 1][ni & 1], b1l = bl[ni >> 1][2 + (ni & 1)]; \
                mma16816(acc[mi][ni], ah[mi], b0h, b1h);                          \
                mma16816(acc[mi][ni], ah[mi], b0l, b1l);                          \
                mma16816(acc[mi][ni], al[mi], b0h, b1h);                          \
            }                                                                     \
    }

// loader: 1024 float4 per tile, 512 threads x 2 iters
#define GEMM_LOADER(NAME, APTR_HI, APTR_LO, BPTR_HI, BPTR_LO, KK, AROW, BROW)     \
    auto NAME = [&](int it) {                                                     \
        const uint32_t bufb = sbase + (it % NSTAGE) * BUFB;                       \
        const int k0 = it * GK;                                                   \
        _Pragma("unroll")                                                         \
        for (int p = 0; p < 2; ++p) {                                             \
            int linear = tid + p * NTHR;                                          \
            int r = linear >> 3;                                                  \
            int cb = (linear & 7) * 16;                                           \
            uint32_t sw = SWZ((uint32_t)(r * 128 + cb));                          \
            size_t ga = (size_t)(AROW + r) * (KK) + k0 + (cb >> 1);               \
            size_t gb = (size_t)(BROW + r) * (KK) + k0 + (cb >> 1);               \
            cp16(bufb + sw,              &(APTR_HI)[ga]);                         \
            cp16(bufb + TILEB + sw,      &(APTR_LO)[ga]);                         \
            cp16(bufb + 2 * TILEB + sw,  &(BPTR_HI)[gb]);                         \
            cp16(bufb + 3 * TILEB + sw,  &(BPTR_LO)[gb]);                         \
        }                                                                         \
    };

// ---------------------------------------------------------------------------
// Fused QKV projection + RoPE + hi/lo split. Logical N = 6144, grid (48, 16).
// ---------------------------------------------------------------------------
__global__ void __launch_bounds__(NTHR, 1)
gemm_qkv(const __nv_bfloat16* __restrict__ Ahi, const __nv_bfloat16* __restrict__ Alo,
         const int* __restrict__ pos,
         __nv_bfloat16* __restrict__ Qh, __nv_bfloat16* __restrict__ Ql,
         __nv_bfloat16* __restrict__ Kh, __nv_bfloat16* __restrict__ Kl,
         __nv_bfloat16* __restrict__ Vh, __nv_bfloat16* __restrict__ Vl)
{
    extern __shared__ char smraw[];
    char* smc = (char*)(((uintptr_t)smraw + 1023) & ~(uintptr_t)1023);
    const uint32_t sbase = smem_u32(smc);

    const int tid = threadIdx.x;
    const int lane = tid & 31;
    const int wid = tid >> 5;
    const int wr = wid >> 2;           // 0..3 -> 32 rows
    const int wc = wid & 3;            // 0..3 -> 32 cols
    const int bx = blockIdx.x;
    const int m0 = blockIdx.y * 128;

    const __nv_bfloat16 *Bhi, *Blo;
    int bn0;
    if (bx < 32)      { Bhi = g_Wq_hi; Blo = g_Wq_lo; bn0 = bx * 128; }
    else if (bx < 40) { Bhi = g_Wk_hi; Blo = g_Wk_lo; bn0 = (bx - 32) * 128; }
    else              { Bhi = g_Wv_hi; Blo = g_Wv_lo; bn0 = (bx - 40) * 128; }

    float acc[2][4][4];
    #pragma unroll
    for (int a = 0; a < 2; ++a)
        #pragma unroll
        for (int b = 0; b < 4; ++b)
            #pragma unroll
            for (int c = 0; c < 4; ++c) acc[a][b][c] = 0.f;

    const int NCHUNK = KDIM / GK;
    GEMM_LOADER(load_chunk, Ahi, Alo, Bhi, Blo, KDIM, m0, bn0)

    load_chunk(0); cp_commit();
    load_chunk(1); cp_commit();

    const int lrow = lane & 15;
    const int lkb  = (lane >> 4) * 16;

    for (int it = 0; it < NCHUNK; ++it) {
        cp_wait<1>();
        __syncthreads();
        if (it + 2 < NCHUNK) load_chunk(it + 2);
        cp_commit();
        const uint32_t bufb = sbase + (it % NSTAGE) * BUFB;
        GEMM_COMPUTE(bufb)
    }

    __syncthreads();   // mainloop smem reads done before Cs reuse

    // ---- epilogue: stage acc in smem, RoPE (Q/K) + split, store bf16 hi/lo ----
    float* Cs = (float*)smc;           // 128 x 132 floats
    {
        const int rb = wr * 32 + (lane >> 2);
        const int cb2 = wc * 32 + (lane & 3) * 2;
        #pragma unroll
        for (int mi = 0; mi < 2; ++mi)
            #pragma unroll
            for (int ni = 0; ni < 4; ++ni) {
                int r = rb + mi * 16, cc = cb2 + ni * 8;
                Cs[r * 132 + cc]           = acc[mi][ni][0];
                Cs[r * 132 + cc + 1]       = acc[mi][ni][1];
                Cs[(r + 8) * 132 + cc]     = acc[mi][ni][2];
                Cs[(r + 8) * 132 + cc + 1] = acc[mi][ni][3];
            }
    }
    __syncthreads();

    __nv_bfloat16 *Hout, *Lout;
    int stride, off;
    bool dorope;
    if (bx < 32)      { Hout = Qh; Lout = Ql; stride = HID;  off = bx * 128;        dorope = true; }
    else if (bx < 40) { Hout = Kh; Lout = Kl; stride = NKVD; off = (bx - 32) * 128; dorope = true; }
    else              { Hout = Vh; Lout = Vl; stride = NKVD; off = (bx - 40) * 128; dorope = false; }

    const int d0 = tid & 63;           // rotation-pair column
    const int rg = tid >> 6;           // 0..7 -> 16 rows each
    const float invf = dorope ? expf(-(float)d0 * 0.14391156831212787f) : 0.f;

    #pragma unroll 4
    for (int rr = 0; rr < 16; ++rr) {
        const int r = rg * 16 + rr;
        const int t = m0 + r;
        float x0 = Cs[r * 132 + d0];
        float x1 = Cs[r * 132 + d0 + 64];
        float y0, y1;
        if (dorope) {
            float s, c;
            sincosf((float)pos[t] * invf, &s, &c);
            y0 = x0 * c - x1 * s;
            y1 = x1 * c + x0 * s;
        } else {
            y0 = x0; y1 = x1;
        }
        __nv_bfloat16 h0 = __float2bfloat16(y0);
        __nv_bfloat16 l0 = __float2bfloat16(y0 - __bfloat162float(h0));
        __nv_bfloat16 h1 = __float2bfloat16(y1);
        __nv_bfloat16 l1 = __float2bfloat16(y1 - __bfloat162float(h1));
        size_t o = (size_t)t * stride + off + d0;
        Hout[o]      = h0;
        Lout[o]      = l0;
        Hout[o + 64] = h1;
        Lout[o + 64] = l1;
    }
}

// ---------------------------------------------------------------------------
// Generic GEMM (Wo projection): C = (Ahi+Alo)*(Bhi+Blo)^T, fp32 out.
// ---------------------------------------------------------------------------
__global__ void __launch_bounds__(NTHR, 1)
gemm_bf16x3(const __nv_bfloat16* __restrict__ Ahi, const __nv_bfloat16* __restrict__ Alo,
            const __nv_bfloat16* __restrict__ Bhi, const __nv_bfloat16* __restrict__ Blo,
            float* __restrict__ C, int M, int N, int K)
{
    extern __shared__ char smraw[];
    char* smc = (char*)(((uintptr_t)smraw + 1023) & ~(uintptr_t)1023);
    const uint32_t sbase = smem_u32(smc);

    const int tid = threadIdx.x;
    const int lane = tid & 31;
    const int wid = tid >> 5;
    const int wr = wid >> 2;
    const int wc = wid & 3;
    const int m0 = blockIdx.y * 128;
    const int n0 = blockIdx.x * 128;

    float acc[2][4][4];
    #pragma unroll
    for (int a = 0; a < 2; ++a)
        #pragma unroll
        for (int b = 0; b < 4; ++b)
            #pragma unroll
            for (int c = 0; c < 4; ++c) acc[a][b][c] = 0.f;

    const int NCHUNK = K / GK;
    GEMM_LOADER(load_chunk, Ahi, Alo, Bhi, Blo, K, m0, n0)

    load_chunk(0); cp_commit();
    load_chunk(1); cp_commit();

    const int lrow = lane & 15;
    const int lkb  = (lane >> 4) * 16;

    for (int it = 0; it < NCHUNK; ++it) {
        cp_wait<1>();
        __syncthreads();
        if (it + 2 < NCHUNK) load_chunk(it + 2);
        cp_commit();
        const uint32_t bufb = sbase + (it % NSTAGE) * BUFB;
        GEMM_COMPUTE(bufb)
    }

    const int row_base = m0 + wr * 32 + (lane >> 2);
    const int col_base = n0 + wc * 32 + (lane & 3) * 2;
    #pragma unroll
    for (int mi = 0; mi < 2; ++mi)
        #pragma unroll
        for (int ni = 0; ni < 4; ++ni) {
            int r = row_base + mi * 16;
            int cc = col_base + ni * 8;
            *(float2*)&C[(size_t)r * N + cc]       = make_float2(acc[mi][ni][0], acc[mi][ni][1]);
            *(float2*)&C[(size_t)(r + 8) * N + cc] = make_float2(acc[mi][ni][2], acc[mi][ni][3]);
        }
}

// ---------------------------------------------------------------------------
// Flash attention on tensor cores (bf16x3, online softmax in registers).
// R8-proven double-buffered KV pipeline. 256 threads.
// ---------------------------------------------------------------------------
#define ATT_SMEM (1024 + 3 * 65536)

__global__ void __launch_bounds__(256)
attn_mma(const __nv_bfloat16* __restrict__ Qh_g, const __nv_bfloat16* __restrict__ Ql_g,
         const __nv_bfloat16* __restrict__ Kh_g, const __nv_bfloat16* __restrict__ Kl_g,
         const __nv_bfloat16* __restrict__ Vh_g, const __nv_bfloat16* __restrict__ Vl_g,
         __nv_bfloat16* __restrict__ Oh_g, __nv_bfloat16* __restrict__ Ol_g)
{
    extern __shared__ char smraw[];
    char* smc = (char*)(((uintptr_t)smraw + 1023) & ~(uintptr_t)1023);
    const uint32_t qbase = smem_u32(smc);
    const uint32_t kvbase = qbase + 65536;

    const int tid = threadIdx.x;
    const int lane = tid & 31;
    const int w = tid >> 5;
    const int wm = w * 16;
    const int m0 = blockIdx.x * 128;
    const int h = blockIdx.y;
    const int kvh = h >> 2;
    const int lrow = lane & 15;
    const int lhi = (lane >> 4) * 16;

    auto load_q = [&]() {
        #pragma unroll
        for (int p = 0; p < 16; ++p) {
            int lin = tid + p * 256;
            int t2 = lin >> 11;
            int rem = lin & 2047;
            int row = rem >> 4;
            int c = rem & 15;
            int half = c >> 3;
            int cb = (c & 7) * 16;
            uint32_t dst = qbase + t2 * 32768 + half * 16384
                         + SWZ((uint32_t)(row * 128 + cb));
            size_t elem = (size_t)(m0 + row) * HID + h * HDIM + half * 64 + (c & 7) * 8;
            cp16(dst, (t2 ? Ql_g : Qh_g) + elem);
        }
    };
    auto load_kv = [&](int j, int b) {
        const uint32_t base = kvbase + b * 65536;
        #pragma unroll
        for (int p = 0; p < 16; ++p) {
            int lin = tid + p * 256;
            int t4 = lin >> 10;
            int rem = lin & 1023;
            int row = rem >> 4;
            int c = rem & 15;
            int half = c >> 3;
            int cb = (c & 7) * 16;
            uint32_t dst = base + t4 * 16384 + half * 8192
                         + SWZ((uint32_t)(row * 128 + cb));
            size_t elem = (size_t)(j * 64 + row) * NKVD + kvh * HDIM
                        + half * 64 + (c & 7) * 8;
            const __nv_bfloat16* src =
                (t4 < 2) ? ((t4 & 1) ? Kl_g : Kh_g) : ((t4 & 1) ? Vl_g : Vh_g);
            cp16(dst, src + elem);
        }
    };

    const int j0 = (m0 >= 1024) ? (m0 - 1023) / 64 : 0;
    const int jend = m0 / 64 + 1;

    load_q();
    load_kv(j0, 0);
    cp_commit();

    float o[16][4];
    #pragma unroll
    for (int i = 0; i < 16; ++i)
        #pragma unroll
        for (int c = 0; c < 4; ++c) o[i][c] = 0.f;
    float mst0 = -INFINITY, mst1 = -INFINITY, lst0 = 0.f, lst1 = 0.f;

    const int row0 = m0 + wm + (lane >> 2);
    const int row1 = row0 + 8;
    const float scale = 0.08838834764831845f;

    for (int j = j0; j <= jend; ++j) {
        const int b = (j - j0) & 1;
        if (j + 1 <= jend) {
            load_kv(j + 1, b ^ 1);
            cp_commit();
            cp_wait<1>();
        } else {
            cp_wait<0>();
        }
        __syncthreads();

        const uint32_t kvb = kvbase + b * 65536;

        float sf[8][4];
        #pragma unroll
        for (int i = 0; i < 8; ++i)
            #pragma unroll
            for (int c = 0; c < 4; ++c) sf[i][c] = 0.f;

        #pragma unroll
        for (int kd = 0; kd < 8; ++kd) {
            const int half = kd >> 2;
            const uint32_t koff = (uint32_t)((kd & 3) * 32 + lhi);
            uint32_t ah[4], al[4], bh[4][4], bl[4][4];
            {
                uint32_t sw = SWZ((uint32_t)((wm + lrow) * 128) + koff);
                ldsm_x4(ah, qbase + half * 16384 + sw);
                ldsm_x4(al, qbase + 32768 + half * 16384 + sw);
            }
            #pragma unroll
            for (int nb = 0; nb < 4; ++nb) {
                uint32_t sw = SWZ((uint32_t)((nb * 16 + lrow) * 128) + koff);
                ldsm_x4(bh[nb], kvb + half * 8192 + sw);
                ldsm_x4(bl[nb], kvb + 16384 + half * 8192 + sw);
            }
            #pragma unroll
            for (int ni = 0; ni < 8; ++ni) {
                const int nb = ni >> 1, s = ni & 1;
                mma16816(sf[ni], ah, bh[nb][s], bh[nb][s + 2]);
                mma16816(sf[ni], ah, bl[nb][s], bl[nb][s + 2]);
                mma16816(sf[ni], al, bh[nb][s], bh[nb][s + 2]);
            }
        }

        const int colb = j * 64 + (lane & 3) * 2;
        float rmax0 = -INFINITY, rmax1 = -INFINITY;
        #pragma unroll
        for (int ni = 0; ni < 8; ++ni) {
            int c0 = colb + ni * 8, c1 = c0 + 1;
            sf[ni][0] = (c0 <= row0 && row0 - c0 < WINDOW) ? sf[ni][0] * scale : -INFINITY;
            sf[ni][1] = (c1 <= row0 && row0 - c1 < WINDOW) ? sf[ni][1] * scale : -INFINITY;
            sf[ni][2] = (c0 <= row1 && row1 - c0 < WINDOW) ? sf[ni][2] * scale : -INFINITY;
            sf[ni][3] = (c1 <= row1 && row1 - c1 < WINDOW) ? sf[ni][3] * scale : -INFINITY;
            rmax0 = fmaxf(rmax0, fmaxf(sf[ni][0], sf[ni][1]));
            rmax1 = fmaxf(rmax1, fmaxf(sf[ni][2], sf[ni][3]));
        }
        rmax0 = fmaxf(rmax0, __shfl_xor_sync(0xffffffffu, rmax0, 1));
        rmax0 = fmaxf(rmax0, __shfl_xor_sync(0xffffffffu, rmax0, 2));
        rmax1 = fmaxf(rmax1, __shfl_xor_sync(0xffffffffu, rmax1, 1));
        rmax1 = fmaxf(rmax1, __shfl_xor_sync(0xffffffffu, rmax1, 2));

        float mn0 = fmaxf(mst0, rmax0), mn1 = fmaxf(mst1, rmax1);
        float mc0 = fmaxf(mn0, -1e30f), mc1 = fmaxf(mn1, -1e30f);
        float a0 = __expf(fmaxf(mst0, -1e30f) - mc0);
        float a1 = __expf(fmaxf(mst1, -1e30f) - mc1);
        float sum0 = 0.f, sum1 = 0.f;
        #pragma unroll
        for (int ni = 0; ni < 8; ++ni) {
            sf[ni][0] = __expf(sf[ni][0] - mc0);
            sf[ni][1] = __expf(sf[ni][1] - mc0);
            sf[ni][2] = __expf(sf[ni][2] - mc1);
            sf[ni][3] = __expf(sf[ni][3] - mc1);
            sum0 += sf[ni][0] + sf[ni][1];
            sum1 += sf[ni][2] + sf[ni][3];
        }
        sum0 += __shfl_xor_sync(0xffffffffu, sum0, 1);
        sum0 += __shfl_xor_sync(0xffffffffu, sum0, 2);
        sum1 += __shfl_xor_sync(0xffffffffu, sum1, 1);
        sum1 += __shfl_xor_sync(0xffffffffu, sum1, 2);
        mst0 = mn0; mst1 = mn1;
        lst0 = lst0 * a0 + sum0;
        lst1 = lst1 * a1 + sum1;
        #pragma unroll
        for (int nf = 0; nf < 16; ++nf) {
            o[nf][0] *= a0; o[nf][1] *= a0;
            o[nf][2] *= a1; o[nf][3] *= a1;
        }

        #pragma unroll
        for (int ks = 0; ks < 4; ++ks) {
            uint32_t ah[4], al[4];
            packsplit(sf[2 * ks][0],     sf[2 * ks][1],     ah[0], al[0]);
            packsplit(sf[2 * ks][2],     sf[2 * ks][3],     ah[1], al[1]);
            packsplit(sf[2 * ks + 1][0], sf[2 * ks + 1][1], ah[2], al[2]);
            packsplit(sf[2 * ks + 1][2], sf[2 * ks + 1][3], ah[3], al[3]);
            #pragma unroll
            for (int g = 0; g < 8; ++g) {
                const int half = g >> 2;
                uint32_t off = SWZ((uint32_t)((ks * 16 + lrow) * 128 + (g & 3) * 32) + lhi);
                uint32_t vh[4], vl[4];
                ldsm_x4_t(vh, kvb + 32768 + half * 8192 + off);
                ldsm_x4_t(vl, kvb + 49152 + half * 8192 + off);
                mma16816(o[2 * g],     ah, vh[0], vh[1]);
                mma16816(o[2 * g],     ah, vl[0], vl[1]);
                mma16816(o[2 * g],     al, vh[0], vh[1]);
                mma16816(o[2 * g + 1], ah, vh[2], vh[3]);
                mma16816(o[2 * g + 1], ah, vl[2], vl[3]);
                mma16816(o[2 * g + 1], al, vh[2], vh[3]);
            }
        }
        __syncthreads();
    }

    const float inv0 = 1.f / lst0;
    const float inv1 = 1.f / lst1;
    #pragma unroll
    for (int nf = 0; nf < 16; ++nf) {
        int d = h * HDIM + nf * 8 + (lane & 3) * 2;
        size_t off0 = (size_t)row0 * HID + d;
        size_t off1 = (size_t)row1 * HID + d;
        uint32_t hi, lo;
        packsplit(o[nf][0] * inv0, o[nf][1] * inv0, hi, lo);
        *(uint32_t*)(Oh_g + off0) = hi;
        *(uint32_t*)(Ol_g + off0) = lo;
        packsplit(o[nf][2] * inv1, o[nf][3] * inv1, hi, lo);
        *(uint32_t*)(Oh_g + off1) = hi;
        *(uint32_t*)(Ol_g + off1) = lo;
    }
}

// ---------------------------------------------------------------------------
extern "C" void kernel_launch(void* const* d_in, const int* in_sizes, int n_in,
                              void* d_out, int out_size)
{
    const float* hs  = (const float*)d_in[0];
    const int*   pos = (const int*)d_in[2];
    const float* Wq  = (const float*)d_in[3];
    const float* Wk  = (const float*)d_in[4];
    const float* Wv  = (const float*)d_in[5];
    const float* Wo  = (const float*)d_in[6];
    float* out = (float*)d_out;

    __nv_bfloat16 *hsh, *hsl, *ath, *atl, *woh, *wol;
    __nv_bfloat16 *qhh, *qll, *khh, *kll, *vhh, *vll;
    cudaGetSymbolAddress((void**)&hsh, g_hs_hi);  cudaGetSymbolAddress((void**)&hsl, g_hs_lo);
    cudaGetSymbolAddress((void**)&ath, g_att_hi); cudaGetSymbolAddress((void**)&atl, g_att_lo);
    cudaGetSymbolAddress((void**)&woh, g_Wo_hi);  cudaGetSymbolAddress((void**)&wol, g_Wo_lo);
    cudaGetSymbolAddress((void**)&qhh, g_Qh);     cudaGetSymbolAddress((void**)&qll, g_Ql);
    cudaGetSymbolAddress((void**)&khh, g_Kh);     cudaGetSymbolAddress((void**)&kll, g_Kl);
    cudaGetSymbolAddress((void**)&vhh, g_Vh);     cudaGetSymbolAddress((void**)&vll, g_Vl);

    cudaFuncSetAttribute(gemm_qkv, cudaFuncAttributeMaxDynamicSharedMemorySize, GEMM_SMEM);
    cudaFuncSetAttribute(gemm_bf16x3, cudaFuncAttributeMaxDynamicSharedMemorySize, GEMM_SMEM);
    cudaFuncSetAttribute(attn_mma, cudaFuncAttributeMaxDynamicSharedMemorySize, ATT_SMEM);

    // single fused split of all fp32 inputs
    split_all<<<(TOT4 + 255) / 256, 256>>>(hs, Wq, Wk, Wv, Wo);

    // fused QKV projection + RoPE + split
    gemm_qkv<<<dim3(48, 16), NTHR, GEMM_SMEM>>>(hsh, hsl, pos,
                                                qhh, qll, khh, kll, vhh, vll);

    // attention (tensor cores), writes bf16 hi/lo directly
    attn_mma<<<dim3(S_LEN / 128, NH), 256, ATT_SMEM>>>(qhh, qll, khh, kll, vhh, vll, ath, atl);

    // output projection
    gemm_bf16x3<<<dim3(HID / 128, S_LEN / 128), NTHR, GEMM_SMEM>>>(ath, atl, woh, wol, out, S_LEN, HID, KDIM);
}

// round 14
// speedup vs baseline: 1.5751x; 1.0040x over previous
#include <cuda_runtime.h>
#include <cuda_bf16.h>
#include <math.h>
#include <stdint.h>

#define S_LEN 2048
#define HID   4096
#define NH    32
#define NKV   8
#define HDIM  128
#define WINDOW 1024
#define KDIM  4096
#define NKVD  (NKV * HDIM)      // 1024

// ---------------- scratch (__device__ globals; no allocation) ----------------
__device__ __align__(256) __nv_bfloat16 g_hs_hi[S_LEN * HID];
__device__ __align__(256) __nv_bfloat16 g_hs_lo[S_LEN * HID];
__device__ __align__(256) __nv_bfloat16 g_att_hi[S_LEN * HID];
__device__ __align__(256) __nv_bfloat16 g_att_lo[S_LEN * HID];
__device__ __align__(256) __nv_bfloat16 g_Qh[S_LEN * HID];
__device__ __align__(256) __nv_bfloat16 g_Ql[S_LEN * HID];
__device__ __align__(256) __nv_bfloat16 g_Kh[S_LEN * NKVD];
__device__ __align__(256) __nv_bfloat16 g_Kl[S_LEN * NKVD];
__device__ __align__(256) __nv_bfloat16 g_Vh[S_LEN * NKVD];
__device__ __align__(256) __nv_bfloat16 g_Vl[S_LEN * NKVD];
__device__ __align__(256) __nv_bfloat16 g_Wq_hi[HID * HID];
__device__ __align__(256) __nv_bfloat16 g_Wq_lo[HID * HID];
__device__ __align__(256) __nv_bfloat16 g_Wk_hi[NKVD * HID];
__device__ __align__(256) __nv_bfloat16 g_Wk_lo[NKVD * HID];
__device__ __align__(256) __nv_bfloat16 g_Wv_hi[NKVD * HID];
__device__ __align__(256) __nv_bfloat16 g_Wv_lo[NKVD * HID];
__device__ __align__(256) __nv_bfloat16 g_Wo_hi[HID * HID];
__device__ __align__(256) __nv_bfloat16 g_Wo_lo[HID * HID];

// ---------------- helpers ----------------
__device__ __forceinline__ uint32_t smem_u32(const void* p) {
    uint32_t a;
    asm("{ .reg .u64 t; cvta.to.shared.u64 t, %1; cvt.u32.u64 %0, t; }" : "=r"(a) : "l"(p));
    return a;
}
__device__ __forceinline__ void cp16(uint32_t dst, const void* src) {
    asm volatile("cp.async.cg.shared.global [%0], [%1], 16;" :: "r"(dst), "l"(src));
}
__device__ __forceinline__ void cp_commit() {
    asm volatile("cp.async.commit_group;" ::: "memory");
}
template <int N>
__device__ __forceinline__ void cp_wait() {
    asm volatile("cp.async.wait_group %0;" :: "n"(N) : "memory");
}
__device__ __forceinline__ void ldsm_x4(uint32_t* r, uint32_t addr) {
    asm volatile("ldmatrix.sync.aligned.m8n8.x4.shared.b16 {%0,%1,%2,%3}, [%4];"
                 : "=r"(r[0]), "=r"(r[1]), "=r"(r[2]), "=r"(r[3]) : "r"(addr));
}
__device__ __forceinline__ void ldsm_x4_t(uint32_t* r, uint32_t addr) {
    asm volatile("ldmatrix.sync.aligned.m8n8.x4.trans.shared.b16 {%0,%1,%2,%3}, [%4];"
                 : "=r"(r[0]), "=r"(r[1]), "=r"(r[2]), "=r"(r[3]) : "r"(addr));
}
// NOTE: no volatile — register-only op, lets the compiler schedule MMAs freely.
__device__ __forceinline__ void mma16816(float* c, const uint32_t* a,
                                         uint32_t b0, uint32_t b1) {
    asm("mma.sync.aligned.m16n8k16.row.col.f32.bf16.bf16.f32 "
        "{%0,%1,%2,%3}, {%4,%5,%6,%7}, {%8,%9}, {%0,%1,%2,%3};"
        : "+f"(c[0]), "+f"(c[1]), "+f"(c[2]), "+f"(c[3])
        : "r"(a[0]), "r"(a[1]), "r"(a[2]), "r"(a[3]), "r"(b0), "r"(b1));
}
__device__ __forceinline__ void packsplit(float x, float y, uint32_t& hi, uint32_t& lo) {
    __nv_bfloat16 hx = __float2bfloat16(x), hy = __float2bfloat16(y);
    __nv_bfloat16 lx = __float2bfloat16(x - __bfloat162float(hx));
    __nv_bfloat16 ly = __float2bfloat16(y - __bfloat162float(hy));
    hi = (uint32_t)__bfloat16_as_ushort(hx) | ((uint32_t)__bfloat16_as_ushort(hy) << 16);
    lo = (uint32_t)__bfloat16_as_ushort(lx) | ((uint32_t)__bfloat16_as_ushort(ly) << 16);
}

#define SWZ(off) ((off) ^ (((off) >> 3) & 0x70))

// ---------------------------------------------------------------------------
// fused split of all fp32 inputs -> bf16 hi + lo (single launch)
// ---------------------------------------------------------------------------
#define HS4 (S_LEN * HID / 4)
#define WQ4 (HID * HID / 4)
#define WK4 (NKVD * HID / 4)
#define WV4 (NKVD * HID / 4)
#define WO4 (HID * HID / 4)
#define TOT4 (HS4 + WQ4 + WK4 + WV4 + WO4)

__global__ void split_all(const float* __restrict__ hs, const float* __restrict__ Wq,
                          const float* __restrict__ Wk, const float* __restrict__ Wv,
                          const float* __restrict__ Wo)
{
    int i = blockIdx.x * blockDim.x + threadIdx.x;
    if (i >= TOT4) return;
    const float* in;
    __nv_bfloat16 *ho, *lo;
    int off;
    if (i < HS4)                         { in = hs; ho = g_hs_hi; lo = g_hs_lo; off = i; }
    else if (i < HS4 + WQ4)              { in = Wq; ho = g_Wq_hi; lo = g_Wq_lo; off = i - HS4; }
    else if (i < HS4 + WQ4 + WK4)        { in = Wk; ho = g_Wk_hi; lo = g_Wk_lo; off = i - HS4 - WQ4; }
    else if (i < HS4 + WQ4 + WK4 + WV4)  { in = Wv; ho = g_Wv_hi; lo = g_Wv_lo; off = i - HS4 - WQ4 - WK4; }
    else                                 { in = Wo; ho = g_Wo_hi; lo = g_Wo_lo; off = i - HS4 - WQ4 - WK4 - WV4; }

    float4 v = ((const float4*)in)[off];
    float x[4] = {v.x, v.y, v.z, v.w};
    unsigned short h[4], l[4];
    #pragma unroll
    for (int j = 0; j < 4; ++j) {
        __nv_bfloat16 hb = __float2bfloat16(x[j]);
        __nv_bfloat16 lb = __float2bfloat16(x[j] - __bfloat162float(hb));
        h[j] = __bfloat16_as_ushort(hb);
        l[j] = __bfloat16_as_ushort(lb);
    }
    ((ushort4*)ho)[off] = make_ushort4(h[0], h[1], h[2], h[3]);
    ((ushort4*)lo)[off] = make_ushort4(l[0], l[1], l[2], l[3]);
}

// ---------------------------------------------------------------------------
// GEMM: 512 threads (16 warps, 4/SMSP), warp tile 32x32, CTA tile 128x128.
// 3-stage cp.async pipeline. Term-major MMA ordering for ILP.
// ---------------------------------------------------------------------------
#define GK 64
#define TILEB 16384
#define BUFB (4 * TILEB)        // 64 KB per stage
#define NSTAGE 3
#define GEMM_SMEM (1024 + NSTAGE * BUFB)
#define NTHR 512

// compute body (warp tile 32x32): acc[2][4][4]; term-major MMA issue order
#define GEMM_COMPUTE(bufb)                                                        \
    _Pragma("unroll")                                                             \
    for (int ks = 0; ks < 4; ++ks) {                                              \
        uint32_t ah[2][4], al[2][4], bh[2][4], bl[2][4];                          \
        _Pragma("unroll")                                                         \
        for (int mi = 0; mi < 2; ++mi) {                                          \
            uint32_t off = (uint32_t)((wr * 32 + mi * 16 + lrow) * 128 + ks * 32 + lkb); \
            uint32_t sw = SWZ(off);                                               \
            ldsm_x4(ah[mi], (bufb) + sw);                                         \
            ldsm_x4(al[mi], (bufb) + TILEB + sw);                                 \
        }                                                                         \
        _Pragma("unroll")                                                         \
        for (int np = 0; np < 2; ++np) {                                          \
            uint32_t off = (uint32_t)((wc * 32 + np * 16 + lrow) * 128 + ks * 32 + lkb); \
            uint32_t sw = SWZ(off);                                               \
            ldsm_x4(bh[np], (bufb) + 2 * TILEB + sw);                             \
            ldsm_x4(bl[np], (bufb) + 3 * TILEB + sw);                             \
        }                                                                         \
        /* term hh: 8 independent MMAs */                                         \
        _Pragma("unroll")                                                         \
        for (int mi = 0; mi < 2; ++mi)                                            \
            _Pragma("unroll")                                                     \
            for (int ni = 0; ni < 4; ++ni)                                        \
                mma16816(acc[mi][ni], ah[mi],                                     \
                         bh[ni >> 1][ni & 1], bh[ni >> 1][2 + (ni & 1)]);         \
        /* term hl */                                                             \
        _Pragma("unroll")                                                         \
        for (int mi = 0; mi < 2; ++mi)                                            \
            _Pragma("unroll")                                                     \
            for (int ni = 0; ni < 4; ++ni)                                        \
                mma16816(acc[mi][ni], ah[mi],                                     \
                         bl[ni >> 1][ni & 1], bl[ni >> 1][2 + (ni & 1)]);         \
        /* term lh */                                                             \
        _Pragma("unroll")                                                         \
        for (int mi = 0; mi < 2; ++mi)                                            \
            _Pragma("unroll")                                                     \
            for (int ni = 0; ni < 4; ++ni)                                        \
                mma16816(acc[mi][ni], al[mi],                                     \
                         bh[ni >> 1][ni & 1], bh[ni >> 1][2 + (ni & 1)]);         \
    }

// loader: 1024 float4 per tile, 512 threads x 2 iters
#define GEMM_LOADER(NAME, APTR_HI, APTR_LO, BPTR_HI, BPTR_LO, KK, AROW, BROW)     \
    auto NAME = [&](int it) {                                                     \
        const uint32_t bufb = sbase + (it % NSTAGE) * BUFB;                       \
        const int k0 = it * GK;                                                   \
        _Pragma("unroll")                                                         \
        for (int p = 0; p < 2; ++p) {                                             \
            int linear = tid + p * NTHR;                                          \
            int r = linear >> 3;                                                  \
            int cb = (linear & 7) * 16;                                           \
            uint32_t sw = SWZ((uint32_t)(r * 128 + cb));                          \
            size_t ga = (size_t)(AROW + r) * (KK) + k0 + (cb >> 1);               \
            size_t gb = (size_t)(BROW + r) * (KK) + k0 + (cb >> 1);               \
            cp16(bufb + sw,              &(APTR_HI)[ga]);                         \
            cp16(bufb + TILEB + sw,      &(APTR_LO)[ga]);                         \
            cp16(bufb + 2 * TILEB + sw,  &(BPTR_HI)[gb]);                         \
            cp16(bufb + 3 * TILEB + sw,  &(BPTR_LO)[gb]);                         \
        }                                                                         \
    };

// ---------------------------------------------------------------------------
// Fused QKV projection + RoPE + hi/lo split. Logical N = 6144, grid (48, 16).
// ---------------------------------------------------------------------------
__global__ void __launch_bounds__(NTHR, 1)
gemm_qkv(const __nv_bfloat16* __restrict__ Ahi, const __nv_bfloat16* __restrict__ Alo,
         const int* __restrict__ pos,
         __nv_bfloat16* __restrict__ Qh, __nv_bfloat16* __restrict__ Ql,
         __nv_bfloat16* __restrict__ Kh, __nv_bfloat16* __restrict__ Kl,
         __nv_bfloat16* __restrict__ Vh, __nv_bfloat16* __restrict__ Vl)
{
    extern __shared__ char smraw[];
    char* smc = (char*)(((uintptr_t)smraw + 1023) & ~(uintptr_t)1023);
    const uint32_t sbase = smem_u32(smc);

    const int tid = threadIdx.x;
    const int lane = tid & 31;
    const int wid = tid >> 5;
    const int wr = wid >> 2;           // 0..3 -> 32 rows
    const int wc = wid & 3;            // 0..3 -> 32 cols
    const int bx = blockIdx.x;
    const int m0 = blockIdx.y * 128;

    const __nv_bfloat16 *Bhi, *Blo;
    int bn0;
    if (bx < 32)      { Bhi = g_Wq_hi; Blo = g_Wq_lo; bn0 = bx * 128; }
    else if (bx < 40) { Bhi = g_Wk_hi; Blo = g_Wk_lo; bn0 = (bx - 32) * 128; }
    else              { Bhi = g_Wv_hi; Blo = g_Wv_lo; bn0 = (bx - 40) * 128; }

    float acc[2][4][4];
    #pragma unroll
    for (int a = 0; a < 2; ++a)
        #pragma unroll
        for (int b = 0; b < 4; ++b)
            #pragma unroll
            for (int c = 0; c < 4; ++c) acc[a][b][c] = 0.f;

    const int NCHUNK = KDIM / GK;
    GEMM_LOADER(load_chunk, Ahi, Alo, Bhi, Blo, KDIM, m0, bn0)

    load_chunk(0); cp_commit();
    load_chunk(1); cp_commit();

    const int lrow = lane & 15;
    const int lkb  = (lane >> 4) * 16;

    for (int it = 0; it < NCHUNK; ++it) {
        cp_wait<1>();
        __syncthreads();
        if (it + 2 < NCHUNK) load_chunk(it + 2);
        cp_commit();
        const uint32_t bufb = sbase + (it % NSTAGE) * BUFB;
        GEMM_COMPUTE(bufb)
    }

    __syncthreads();   // mainloop smem reads done before Cs reuse

    // ---- epilogue: stage acc in smem, RoPE (Q/K) + split, store bf16 hi/lo ----
    float* Cs = (float*)smc;           // 128 x 132 floats
    {
        const int rb = wr * 32 + (lane >> 2);
        const int cb2 = wc * 32 + (lane & 3) * 2;
        #pragma unroll
        for (int mi = 0; mi < 2; ++mi)
            #pragma unroll
            for (int ni = 0; ni < 4; ++ni) {
                int r = rb + mi * 16, cc = cb2 + ni * 8;
                Cs[r * 132 + cc]           = acc[mi][ni][0];
                Cs[r * 132 + cc + 1]       = acc[mi][ni][1];
                Cs[(r + 8) * 132 + cc]     = acc[mi][ni][2];
                Cs[(r + 8) * 132 + cc + 1] = acc[mi][ni][3];
            }
    }
    __syncthreads();

    __nv_bfloat16 *Hout, *Lout;
    int stride, off;
    bool dorope;
    if (bx < 32)      { Hout = Qh; Lout = Ql; stride = HID;  off = bx * 128;        dorope = true; }
    else if (bx < 40) { Hout = Kh; Lout = Kl; stride = NKVD; off = (bx - 32) * 128; dorope = true; }
    else              { Hout = Vh; Lout = Vl; stride = NKVD; off = (bx - 40) * 128; dorope = false; }

    const int d0 = tid & 63;           // rotation-pair column
    const int rg = tid >> 6;           // 0..7 -> 16 rows each
    const float invf = dorope ? expf(-(float)d0 * 0.14391156831212787f) : 0.f;

    #pragma unroll 4
    for (int rr = 0; rr < 16; ++rr) {
        const int r = rg * 16 + rr;
        const int t = m0 + r;
        float x0 = Cs[r * 132 + d0];
        float x1 = Cs[r * 132 + d0 + 64];
        float y0, y1;
        if (dorope) {
            float s, c;
            sincosf((float)pos[t] * invf, &s, &c);
            y0 = x0 * c - x1 * s;
            y1 = x1 * c + x0 * s;
        } else {
            y0 = x0; y1 = x1;
        }
        __nv_bfloat16 h0 = __float2bfloat16(y0);
        __nv_bfloat16 l0 = __float2bfloat16(y0 - __bfloat162float(h0));
        __nv_bfloat16 h1 = __float2bfloat16(y1);
        __nv_bfloat16 l1 = __float2bfloat16(y1 - __bfloat162float(h1));
        size_t o = (size_t)t * stride + off + d0;
        Hout[o]      = h0;
        Lout[o]      = l0;
        Hout[o + 64] = h1;
        Lout[o + 64] = l1;
    }
}

// ---------------------------------------------------------------------------
// Generic GEMM (Wo projection): C = (Ahi+Alo)*(Bhi+Blo)^T, fp32 out.
// ---------------------------------------------------------------------------
__global__ void __launch_bounds__(NTHR, 1)
gemm_bf16x3(const __nv_bfloat16* __restrict__ Ahi, const __nv_bfloat16* __restrict__ Alo,
            const __nv_bfloat16* __restrict__ Bhi, const __nv_bfloat16* __restrict__ Blo,
            float* __restrict__ C, int M, int N, int K)
{
    extern __shared__ char smraw[];
    char* smc = (char*)(((uintptr_t)smraw + 1023) & ~(uintptr_t)1023);
    const uint32_t sbase = smem_u32(smc);

    const int tid = threadIdx.x;
    const int lane = tid & 31;
    const int wid = tid >> 5;
    const int wr = wid >> 2;
    const int wc = wid & 3;
    const int m0 = blockIdx.y * 128;
    const int n0 = blockIdx.x * 128;

    float acc[2][4][4];
    #pragma unroll
    for (int a = 0; a < 2; ++a)
        #pragma unroll
        for (int b = 0; b < 4; ++b)
            #pragma unroll
            for (int c = 0; c < 4; ++c) acc[a][b][c] = 0.f;

    const int NCHUNK = K / GK;
    GEMM_LOADER(load_chunk, Ahi, Alo, Bhi, Blo, K, m0, n0)

    load_chunk(0); cp_commit();
    load_chunk(1); cp_commit();

    const int lrow = lane & 15;
    const int lkb  = (lane >> 4) * 16;

    for (int it = 0; it < NCHUNK; ++it) {
        cp_wait<1>();
        __syncthreads();
        if (it + 2 < NCHUNK) load_chunk(it + 2);
        cp_commit();
        const uint32_t bufb = sbase + (it % NSTAGE) * BUFB;
        GEMM_COMPUTE(bufb)
    }

    const int row_base = m0 + wr * 32 + (lane >> 2);
    const int col_base = n0 + wc * 32 + (lane & 3) * 2;
    #pragma unroll
    for (int mi = 0; mi < 2; ++mi)
        #pragma unroll
        for (int ni = 0; ni < 4; ++ni) {
            int r = row_base + mi * 16;
            int cc = col_base + ni * 8;
            *(float2*)&C[(size_t)r * N + cc]       = make_float2(acc[mi][ni][0], acc[mi][ni][1]);
            *(float2*)&C[(size_t)(r + 8) * N + cc] = make_float2(acc[mi][ni][2], acc[mi][ni][3]);
        }
}

// ---------------------------------------------------------------------------
// Flash attention on tensor cores (bf16x3, online softmax in registers).
// Term-major S MMAs; interleaved PV MMAs. 256 threads.
// ---------------------------------------------------------------------------
#define ATT_SMEM (1024 + 3 * 65536)

__global__ void __launch_bounds__(256)
attn_mma(const __nv_bfloat16* __restrict__ Qh_g, const __nv_bfloat16* __restrict__ Ql_g,
         const __nv_bfloat16* __restrict__ Kh_g, const __nv_bfloat16* __restrict__ Kl_g,
         const __nv_bfloat16* __restrict__ Vh_g, const __nv_bfloat16* __restrict__ Vl_g,
         __nv_bfloat16* __restrict__ Oh_g, __nv_bfloat16* __restrict__ Ol_g)
{
    extern __shared__ char smraw[];
    char* smc = (char*)(((uintptr_t)smraw + 1023) & ~(uintptr_t)1023);
    const uint32_t qbase = smem_u32(smc);
    const uint32_t kvbase = qbase + 65536;

    const int tid = threadIdx.x;
    const int lane = tid & 31;
    const int w = tid >> 5;
    const int wm = w * 16;
    const int m0 = blockIdx.x * 128;
    const int h = blockIdx.y;
    const int kvh = h >> 2;
    const int lrow = lane & 15;
    const int lhi = (lane >> 4) * 16;

    auto load_q = [&]() {
        #pragma unroll
        for (int p = 0; p < 16; ++p) {
            int lin = tid + p * 256;
            int t2 = lin >> 11;
            int rem = lin & 2047;
            int row = rem >> 4;
            int c = rem & 15;
            int half = c >> 3;
            int cb = (c & 7) * 16;
            uint32_t dst = qbase + t2 * 32768 + half * 16384
                         + SWZ((uint32_t)(row * 128 + cb));
            size_t elem = (size_t)(m0 + row) * HID + h * HDIM + half * 64 + (c & 7) * 8;
            cp16(dst, (t2 ? Ql_g : Qh_g) + elem);
        }
    };
    auto load_kv = [&](int j, int b) {
        const uint32_t base = kvbase + b * 65536;
        #pragma unroll
        for (int p = 0; p < 16; ++p) {
            int lin = tid + p * 256;
            int t4 = lin >> 10;
            int rem = lin & 1023;
            int row = rem >> 4;
            int c = rem & 15;
            int half = c >> 3;
            int cb = (c & 7) * 16;
            uint32_t dst = base + t4 * 16384 + half * 8192
                         + SWZ((uint32_t)(row * 128 + cb));
            size_t elem = (size_t)(j * 64 + row) * NKVD + kvh * HDIM
                        + half * 64 + (c & 7) * 8;
            const __nv_bfloat16* src =
                (t4 < 2) ? ((t4 & 1) ? Kl_g : Kh_g) : ((t4 & 1) ? Vl_g : Vh_g);
            cp16(dst, src + elem);
        }
    };

    const int j0 = (m0 >= 1024) ? (m0 - 1023) / 64 : 0;
    const int jend = m0 / 64 + 1;

    load_q();
    load_kv(j0, 0);
    cp_commit();

    float o[16][4];
    #pragma unroll
    for (int i = 0; i < 16; ++i)
        #pragma unroll
        for (int c = 0; c < 4; ++c) o[i][c] = 0.f;
    float mst0 = -INFINITY, mst1 = -INFINITY, lst0 = 0.f, lst1 = 0.f;

    const int row0 = m0 + wm + (lane >> 2);
    const int row1 = row0 + 8;
    const float scale = 0.08838834764831845f;

    for (int j = j0; j <= jend; ++j) {
        const int b = (j - j0) & 1;
        if (j + 1 <= jend) {
            load_kv(j + 1, b ^ 1);
            cp_commit();
            cp_wait<1>();
        } else {
            cp_wait<0>();
        }
        __syncthreads();

        const uint32_t kvb = kvbase + b * 65536;

        float sf[8][4];
        #pragma unroll
        for (int i = 0; i < 8; ++i)
            #pragma unroll
            for (int c = 0; c < 4; ++c) sf[i][c] = 0.f;

        #pragma unroll
        for (int kd = 0; kd < 8; ++kd) {
            const int half = kd >> 2;
            const uint32_t koff = (uint32_t)((kd & 3) * 32 + lhi);
            uint32_t ah[4], al[4], bh[4][4], bl[4][4];
            {
                uint32_t sw = SWZ((uint32_t)((wm + lrow) * 128) + koff);
                ldsm_x4(ah, qbase + half * 16384 + sw);
                ldsm_x4(al, qbase + 32768 + half * 16384 + sw);
            }
            #pragma unroll
            for (int nb = 0; nb < 4; ++nb) {
                uint32_t sw = SWZ((uint32_t)((nb * 16 + lrow) * 128) + koff);
                ldsm_x4(bh[nb], kvb + half * 8192 + sw);
                ldsm_x4(bl[nb], kvb + 16384 + half * 8192 + sw);
            }
            // term-major: 8 independent MMAs per term
            #pragma unroll
            for (int ni = 0; ni < 8; ++ni) {
                const int nb = ni >> 1, s = ni & 1;
                mma16816(sf[ni], ah, bh[nb][s], bh[nb][s + 2]);
            }
            #pragma unroll
            for (int ni = 0; ni < 8; ++ni) {
                const int nb = ni >> 1, s = ni & 1;
                mma16816(sf[ni], ah, bl[nb][s], bl[nb][s + 2]);
            }
            #pragma unroll
            for (int ni = 0; ni < 8; ++ni) {
                const int nb = ni >> 1, s = ni & 1;
                mma16816(sf[ni], al, bh[nb][s], bh[nb][s + 2]);
            }
        }

        const int colb = j * 64 + (lane & 3) * 2;
        float rmax0 = -INFINITY, rmax1 = -INFINITY;
        #pragma unroll
        for (int ni = 0; ni < 8; ++ni) {
            int c0 = colb + ni * 8, c1 = c0 + 1;
            sf[ni][0] = (c0 <= row0 && row0 - c0 < WINDOW) ? sf[ni][0] * scale : -INFINITY;
            sf[ni][1] = (c1 <= row0 && row0 - c1 < WINDOW) ? sf[ni][1] * scale : -INFINITY;
            sf[ni][2] = (c0 <= row1 && row1 - c0 < WINDOW) ? sf[ni][2] * scale : -INFINITY;
            sf[ni][3] = (c1 <= row1 && row1 - c1 < WINDOW) ? sf[ni][3] * scale : -INFINITY;
            rmax0 = fmaxf(rmax0, fmaxf(sf[ni][0], sf[ni][1]));
            rmax1 = fmaxf(rmax1, fmaxf(sf[ni][2], sf[ni][3]));
        }
        rmax0 = fmaxf(rmax0, __shfl_xor_sync(0xffffffffu, rmax0, 1));
        rmax0 = fmaxf(rmax0, __shfl_xor_sync(0xffffffffu, rmax0, 2));
        rmax1 = fmaxf(rmax1, __shfl_xor_sync(0xffffffffu, rmax1, 1));
        rmax1 = fmaxf(rmax1, __shfl_xor_sync(0xffffffffu, rmax1, 2));

        float mn0 = fmaxf(mst0, rmax0), mn1 = fmaxf(mst1, rmax1);
        float mc0 = fmaxf(mn0, -1e30f), mc1 = fmaxf(mn1, -1e30f);
        float a0 = __expf(fmaxf(mst0, -1e30f) - mc0);
        float a1 = __expf(fmaxf(mst1, -1e30f) - mc1);
        float sum0 = 0.f, sum1 = 0.f;
        #pragma unroll
        for (int ni = 0; ni < 8; ++ni) {
            sf[ni][0] = __expf(sf[ni][0] - mc0);
            sf[ni][1] = __expf(sf[ni][1] - mc0);
            sf[ni][2] = __expf(sf[ni][2] - mc1);
            sf[ni][3] = __expf(sf[ni][3] - mc1);
            sum0 += sf[ni][0] + sf[ni][1];
            sum1 += sf[ni][2] + sf[ni][3];
        }
        sum0 += __shfl_xor_sync(0xffffffffu, sum0, 1);
        sum0 += __shfl_xor_sync(0xffffffffu, sum0, 2);
        sum1 += __shfl_xor_sync(0xffffffffu, sum1, 1);
        sum1 += __shfl_xor_sync(0xffffffffu, sum1, 2);
        mst0 = mn0; mst1 = mn1;
        lst0 = lst0 * a0 + sum0;
        lst1 = lst1 * a1 + sum1;
        #pragma unroll
        for (int nf = 0; nf < 16; ++nf) {
            o[nf][0] *= a0; o[nf][1] *= a0;
            o[nf][2] *= a1; o[nf][3] *= a1;
        }

        #pragma unroll
        for (int ks = 0; ks < 4; ++ks) {
            uint32_t ah[4], al[4];
            packsplit(sf[2 * ks][0],     sf[2 * ks][1],     ah[0], al[0]);
            packsplit(sf[2 * ks][2],     sf[2 * ks][3],     ah[1], al[1]);
            packsplit(sf[2 * ks + 1][0], sf[2 * ks + 1][1], ah[2], al[2]);
            packsplit(sf[2 * ks + 1][2], sf[2 * ks + 1][3], ah[3], al[3]);
            #pragma unroll
            for (int g = 0; g < 8; ++g) {
                const int half = g >> 2;
                uint32_t off = SWZ((uint32_t)((ks * 16 + lrow) * 128 + (g & 3) * 32) + lhi);
                uint32_t vh[4], vl[4];
                ldsm_x4_t(vh, kvb + 32768 + half * 8192 + off);
                ldsm_x4_t(vl, kvb + 49152 + half * 8192 + off);
                // interleave the two accumulators term by term
                mma16816(o[2 * g],     ah, vh[0], vh[1]);
                mma16816(o[2 * g + 1], ah, vh[2], vh[3]);
                mma16816(o[2 * g],     ah, vl[0], vl[1]);
                mma16816(o[2 * g + 1], ah, vl[2], vl[3]);
                mma16816(o[2 * g],     al, vh[0], vh[1]);
                mma16816(o[2 * g + 1], al, vh[2], vh[3]);
            }
        }
        __syncthreads();
    }

    const float inv0 = 1.f / lst0;
    const float inv1 = 1.f / lst1;
    #pragma unroll
    for (int nf = 0; nf < 16; ++nf) {
        int d = h * HDIM + nf * 8 + (lane & 3) * 2;
        size_t off0 = (size_t)row0 * HID + d;
        size_t off1 = (size_t)row1 * HID + d;
        uint32_t hi, lo;
        packsplit(o[nf][0] * inv0, o[nf][1] * inv0, hi, lo);
        *(uint32_t*)(Oh_g + off0) = hi;
        *(uint32_t*)(Ol_g + off0) = lo;
        packsplit(o[nf][2] * inv1, o[nf][3] * inv1, hi, lo);
        *(uint32_t*)(Oh_g + off1) = hi;
        *(uint32_t*)(Ol_g + off1) = lo;
    }
}

// ---------------------------------------------------------------------------
extern "C" void kernel_launch(void* const* d_in, const int* in_sizes, int n_in,
                              void* d_out, int out_size)
{
    const float* hs  = (const float*)d_in[0];
    const int*   pos = (const int*)d_in[2];
    const float* Wq  = (const float*)d_in[3];
    const float* Wk  = (const float*)d_in[4];
    const float* Wv  = (const float*)d_in[5];
    const float* Wo  = (const float*)d_in[6];
    float* out = (float*)d_out;

    __nv_bfloat16 *hsh, *hsl, *ath, *atl, *woh, *wol;
    __nv_bfloat16 *qhh, *qll, *khh, *kll, *vhh, *vll;
    cudaGetSymbolAddress((void**)&hsh, g_hs_hi);  cudaGetSymbolAddress((void**)&hsl, g_hs_lo);
    cudaGetSymbolAddress((void**)&ath, g_att_hi); cudaGetSymbolAddress((void**)&atl, g_att_lo);
    cudaGetSymbolAddress((void**)&woh, g_Wo_hi);  cudaGetSymbolAddress((void**)&wol, g_Wo_lo);
    cudaGetSymbolAddress((void**)&qhh, g_Qh);     cudaGetSymbolAddress((void**)&qll, g_Ql);
    cudaGetSymbolAddress((void**)&khh, g_Kh);     cudaGetSymbolAddress((void**)&kll, g_Kl);
    cudaGetSymbolAddress((void**)&vhh, g_Vh);     cudaGetSymbolAddress((void**)&vll, g_Vl);

    cudaFuncSetAttribute(gemm_qkv, cudaFuncAttributeMaxDynamicSharedMemorySize, GEMM_SMEM);
    cudaFuncSetAttribute(gemm_bf16x3, cudaFuncAttributeMaxDynamicSharedMemorySize, GEMM_SMEM);
    cudaFuncSetAttribute(attn_mma, cudaFuncAttributeMaxDynamicSharedMemorySize, ATT_SMEM);

    // single fused split of all fp32 inputs
    split_all<<<(TOT4 + 255) / 256, 256>>>(hs, Wq, Wk, Wv, Wo);

    // fused QKV projection + RoPE + split
    gemm_qkv<<<dim3(48, 16), NTHR, GEMM_SMEM>>>(hsh, hsl, pos,
                                                qhh, qll, khh, kll, vhh, vll);

    // attention (tensor cores), writes bf16 hi/lo directly
    attn_mma<<<dim3(S_LEN / 128, NH), 256, ATT_SMEM>>>(qhh, qll, khh, kll, vhh, vll, ath, atl);

    // output projection
    gemm_bf16x3<<<dim3(HID / 128, S_LEN / 128), NTHR, GEMM_SMEM>>>(ath, atl, woh, wol, out, S_LEN, HID, KDIM);
}